// round 2
// baseline (speedup 1.0000x reference)
#include <cuda_runtime.h>
#include <math.h>

#define NN 100000
#define EE 1600000
#define GG 2048
#define NCOUT 204

// ---------------- static scratch (no runtime allocation allowed) ----------------
__device__ float g_bufA[NN * 128];       // t (GEMM input) per layer
__device__ float g_bufB[NN * 128];       // y (pre-BN GEMM output) per layer
__device__ int   g_rowptr[NN + 1];
__device__ int   g_cursor[NN];
__device__ int   g_col[EE];
__device__ float g_stats[8 * 1024];      // per-layer [sum(0..C) | sumsq(C..2C)]
__device__ float g_scale[512];
__device__ float g_shift[512];
__device__ float g_xg[GG * 128];
__device__ float g_m1[GG * 512];
__device__ float g_m2[GG * 256];

// ---------------- packed fp32x2 helpers (sm_100a FFMA2 path) ----------------
#define PACK2(d, x, y) asm("mov.b64 %0, {%1, %2};" : "=l"(d) : "f"(x), "f"(y))
#define UNPACK2(x, y, d) asm("mov.b64 {%0, %1}, %2;" : "=f"(x), "=f"(y) : "l"(d))
#define FFMA2(d, a, b, c) \
    asm("fma.rn.f32x2 %0, %1, %2, %3;" : "=l"(d) : "l"(a), "l"(b), "l"(c))

// ---------------- CSR build ----------------
__global__ void hist_kernel(const int* __restrict__ edst) {
    int e = blockIdx.x * blockDim.x + threadIdx.x;
    if (e < EE) atomicAdd(&g_rowptr[edst[e] + 1], 1);
}

__global__ void scan_kernel(int* a, int n) {
    __shared__ int s[1024];
    __shared__ int carry;
    if (threadIdx.x == 0) carry = 0;
    __syncthreads();
    for (int base = 0; base < n; base += 1024) {
        int i = base + threadIdx.x;
        int v = (i < n) ? a[i] : 0;
        s[threadIdx.x] = v;
        __syncthreads();
        for (int off = 1; off < 1024; off <<= 1) {
            int t = (threadIdx.x >= off) ? s[threadIdx.x - off] : 0;
            __syncthreads();
            s[threadIdx.x] += t;
            __syncthreads();
        }
        int total = s[1023];
        if (i < n) a[i] = s[threadIdx.x] + carry;
        __syncthreads();
        if (threadIdx.x == 0) carry += total;
        __syncthreads();
    }
}

__global__ void fill_kernel(const int* __restrict__ esrc, const int* __restrict__ edst) {
    int e = blockIdx.x * blockDim.x + threadIdx.x;
    if (e >= EE) return;
    int d = edst[e];
    int pos = atomicAdd(&g_cursor[d], 1);
    g_col[g_rowptr[d] + pos] = esrc[e];
}

// ---------------- layer 0 aggregation: t = 2*h + sum_in(h), 78 dims ----------------
__global__ void agg0_kernel(const float* __restrict__ H) {
    int w = (blockIdx.x * blockDim.x + threadIdx.x) >> 5;
    if (w >= NN) return;
    int lid = threadIdx.x & 31;
    const float* hr = H + (size_t)w * 78;
    float a0 = 2.f * hr[lid];
    float a1 = 2.f * hr[lid + 32];
    float a2 = (lid < 14) ? 2.f * hr[lid + 64] : 0.f;
    int beg = g_rowptr[w], end = g_rowptr[w + 1];
    for (int j = beg; j < end; ++j) {
        int s = g_col[j];
        const float* hs = H + (size_t)s * 78;
        a0 += hs[lid];
        a1 += hs[lid + 32];
        if (lid < 14) a2 += hs[lid + 64];
    }
    float* t = g_bufA + (size_t)w * 128;
    t[lid] = a0;
    t[lid + 32] = a1;
    if (lid < 14) t[lid + 64] = a2;
}

// ---------------- mid-layer aggregation (128 dims), BN+ReLU fused on the read side --------
__global__ void agg_kernel(const float* __restrict__ Yin, float* __restrict__ Tout,
                           const float* __restrict__ scale, const float* __restrict__ shift) {
    int w = (blockIdx.x * blockDim.x + threadIdx.x) >> 5;
    if (w >= NN) return;
    int lid = threadIdx.x & 31;
    float4 sc = *(const float4*)&scale[lid * 4];
    float4 sh = *(const float4*)&shift[lid * 4];
    const float4* Y4 = (const float4*)Yin;
    float4 v = Y4[(size_t)w * 32 + lid];
    float a0 = 2.f * fmaxf(0.f, v.x * sc.x + sh.x);
    float a1 = 2.f * fmaxf(0.f, v.y * sc.y + sh.y);
    float a2 = 2.f * fmaxf(0.f, v.z * sc.z + sh.z);
    float a3 = 2.f * fmaxf(0.f, v.w * sc.w + sh.w);
    int beg = g_rowptr[w], end = g_rowptr[w + 1];
    for (int j = beg; j < end; ++j) {
        int s = g_col[j];
        float4 u = Y4[(size_t)s * 32 + lid];
        a0 += fmaxf(0.f, u.x * sc.x + sh.x);
        a1 += fmaxf(0.f, u.y * sc.y + sh.y);
        a2 += fmaxf(0.f, u.z * sc.z + sh.z);
        a3 += fmaxf(0.f, u.w * sc.w + sh.w);
    }
    float4 o = make_float4(a0, a1, a2, a3);
    ((float4*)Tout)[(size_t)w * 32 + lid] = o;
}

// ---------------- readout: xg[graph] += relu(bn(y[n])) ----------------
__global__ void readout_kernel(const float* __restrict__ Yin, const int* __restrict__ gid,
                               const float* __restrict__ scale, const float* __restrict__ shift) {
    int w = (blockIdx.x * blockDim.x + threadIdx.x) >> 5;
    if (w >= NN) return;
    int lid = threadIdx.x & 31;
    float4 sc = *(const float4*)&scale[lid * 4];
    float4 sh = *(const float4*)&shift[lid * 4];
    float4 v = ((const float4*)Yin)[(size_t)w * 32 + lid];
    int g = gid[w];
    float* dst = &g_xg[(size_t)g * 128 + lid * 4];
    atomicAdd(dst + 0, fmaxf(0.f, v.x * sc.x + sh.x));
    atomicAdd(dst + 1, fmaxf(0.f, v.y * sc.y + sh.y));
    atomicAdd(dst + 2, fmaxf(0.f, v.z * sc.z + sh.z));
    atomicAdd(dst + 3, fmaxf(0.f, v.w * sc.w + sh.w));
}

// ---------------- GEMM: Y[rows,128] = T[rows,128(K valid)] @ W[K,128] + bscale*bias ------
// 64x128 block tile, 256 threads, 4x8 outputs/thread via packed f32x2 FMA.
// Fused per-column sum/sumsq for BN stats.
__global__ void __launch_bounds__(256) gemm64x128_kernel(
    const float* __restrict__ T, const float* __restrict__ W,
    const float* __restrict__ bias, float bscale, int rows, int K,
    float* __restrict__ Y, float* __restrict__ stats) {
    extern __shared__ float sm[];
    float* Ws = sm;              // [128][128] (K zero-padded)
    float* Ts = sm + 128 * 128;  // [64][128]
    int tid = threadIdx.x;
    int row0 = blockIdx.x * 64;
    int nrows = rows - row0; if (nrows > 64) nrows = 64;

    for (int idx = tid; idx < 128 * 128; idx += 256) {
        int k = idx >> 7;
        Ws[idx] = (k < K) ? W[idx] : 0.f;
    }
    for (int idx = tid; idx < 64 * 128; idx += 256) {
        int r = idx >> 7, k = idx & 127;
        Ts[idx] = (r < nrows && k < K) ? T[(size_t)(row0 + r) * 128 + k] : 0.f;
    }
    __syncthreads();

    int tx = tid & 15;   // 16 col-groups of 8 cols
    int ty = tid >> 4;   // 16 row-groups of 4 rows
    unsigned long long acc[4][4];
#pragma unroll
    for (int i = 0; i < 4; i++)
#pragma unroll
        for (int p = 0; p < 4; p++) acc[i][p] = 0ull;

    for (int k = 0; k < 128; k += 4) {
        float4 t4[4];
#pragma unroll
        for (int i = 0; i < 4; i++)
            t4[i] = *(const float4*)&Ts[(ty * 4 + i) * 128 + k];
#pragma unroll
        for (int kk = 0; kk < 4; kk++) {
            float4 wa = *(const float4*)&Ws[(k + kk) * 128 + tx * 8];
            float4 wb = *(const float4*)&Ws[(k + kk) * 128 + tx * 8 + 4];
            unsigned long long wp0, wp1, wp2, wp3;
            PACK2(wp0, wa.x, wa.y);
            PACK2(wp1, wa.z, wa.w);
            PACK2(wp2, wb.x, wb.y);
            PACK2(wp3, wb.z, wb.w);
#pragma unroll
            for (int i = 0; i < 4; i++) {
                float tv = (kk == 0) ? t4[i].x : (kk == 1) ? t4[i].y
                         : (kk == 2) ? t4[i].z : t4[i].w;
                unsigned long long td;
                PACK2(td, tv, tv);
                FFMA2(acc[i][0], td, wp0, acc[i][0]);
                FFMA2(acc[i][1], td, wp1, acc[i][1]);
                FFMA2(acc[i][2], td, wp2, acc[i][2]);
                FFMA2(acc[i][3], td, wp3, acc[i][3]);
            }
        }
    }

    // epilogue: bias, store, per-column stats
    float bcol[8];
#pragma unroll
    for (int j = 0; j < 8; j++) bcol[j] = bscale * bias[tx * 8 + j];
    float csum[8], csq[8];
#pragma unroll
    for (int j = 0; j < 8; j++) { csum[j] = 0.f; csq[j] = 0.f; }
#pragma unroll
    for (int i = 0; i < 4; i++) {
        int r = ty * 4 + i;
        if (r < nrows) {
            float v[8];
#pragma unroll
            for (int p = 0; p < 4; p++) UNPACK2(v[2 * p], v[2 * p + 1], acc[i][p]);
#pragma unroll
            for (int j = 0; j < 8; j++) {
                v[j] += bcol[j];
                csum[j] += v[j];
                csq[j] += v[j] * v[j];
            }
            float4 o0 = make_float4(v[0], v[1], v[2], v[3]);
            float4 o1 = make_float4(v[4], v[5], v[6], v[7]);
            float* yr = Y + (size_t)(row0 + r) * 128 + tx * 8;
            *(float4*)yr = o0;
            *(float4*)(yr + 4) = o1;
        }
    }
    __syncthreads();
    float* ss = sm;  // reuse: 256 floats (sum[128] | sumsq[128])
    ss[tid] = 0.f;
    __syncthreads();
#pragma unroll
    for (int j = 0; j < 8; j++) {
        atomicAdd(&ss[tx * 8 + j], csum[j]);
        atomicAdd(&ss[128 + tx * 8 + j], csq[j]);
    }
    __syncthreads();
    if (tid < 128) {
        atomicAdd(&stats[tid], ss[tid]);
        atomicAdd(&stats[128 + tid], ss[128 + tid]);
    }
}

// ---------------- BN coefficient finalize ----------------
__global__ void finalize_kernel(const float* __restrict__ stats, const float* __restrict__ gamma,
                                const float* __restrict__ beta, float invn, int C,
                                float* __restrict__ scale, float* __restrict__ shift) {
    int c = blockIdx.x * blockDim.x + threadIdx.x;
    if (c >= C) return;
    float mu = stats[c] * invn;
    float var = stats[C + c] * invn - mu * mu;
    float inv = rsqrtf(var + 1e-5f);
    float s = gamma[c] * inv;
    scale[c] = s;
    shift[c] = beta[c] - mu * s;
}

// ---------------- small MLP GEMM (thread-per-output) ----------------
__global__ void gemm_small_kernel(const float* __restrict__ X, const float* __restrict__ W,
                                  const float* __restrict__ bias, int R, int K, int C,
                                  float* __restrict__ Y, float* __restrict__ stats) {
    int c = blockIdx.x * 32 + (threadIdx.x & 31);
    int r = blockIdx.y * 8 + (threadIdx.x >> 5);
    if (c >= C || r >= R) return;
    float acc = bias[c];
    const float* xr = X + (size_t)r * K;
    for (int k = 0; k < K; ++k) acc = fmaf(xr[k], W[(size_t)k * C + c], acc);
    Y[(size_t)r * C + c] = acc;
    atomicAdd(&stats[c], acc);
    atomicAdd(&stats[C + c], acc * acc);
}

__global__ void norm_relu_kernel(float* __restrict__ Y, const float* __restrict__ scale,
                                 const float* __restrict__ shift, int total, int C) {
    int i = blockIdx.x * blockDim.x + threadIdx.x;
    if (i >= total) return;
    int c = i % C;
    float v = Y[i] * scale[c] + shift[c];
    Y[i] = fmaxf(v, 0.f);
}

__global__ void fc2_kernel(const float* __restrict__ X, const float* __restrict__ W,
                           const float* __restrict__ bias, float* __restrict__ out) {
    int c = blockIdx.x * 32 + (threadIdx.x & 31);
    int g = blockIdx.y * 8 + (threadIdx.x >> 5);
    if (c >= NCOUT || g >= GG) return;
    float acc = bias[204 + c];
    const float* xr = X + (size_t)g * 256;
    for (int k = 0; k < 256; ++k) acc = fmaf(xr[k], W[(size_t)k * 408 + 204 + c], acc);
    out[(size_t)g * NCOUT + c] = 1.f / (1.f + expf(-acc));
}

// ---------------- host orchestration ----------------
extern "C" void kernel_launch(void* const* d_in, const int* in_sizes, int n_in,
                              void* d_out, int out_size) {
    const float* h        = (const float*)d_in[0];
    const int*   esrc     = (const int*)d_in[1];
    const int*   edst     = (const int*)d_in[2];
    const int*   gid      = (const int*)d_in[3];
    const float* W1       = (const float*)d_in[4];
    const float* b1       = (const float*)d_in[5];
    const float* g1_gamma = (const float*)d_in[6];
    const float* g1_beta  = (const float*)d_in[7];
    const float* Wg       = (const float*)d_in[8];
    const float* bg       = (const float*)d_in[9];
    const float* gg       = (const float*)d_in[10];
    const float* gb       = (const float*)d_in[11];
    const float* fc1_W    = (const float*)d_in[12];
    const float* fc1_b    = (const float*)d_in[13];
    const float* bn1_g    = (const float*)d_in[14];
    const float* bn1_b    = (const float*)d_in[15];
    const float* lin_W    = (const float*)d_in[16];
    const float* lin_b    = (const float*)d_in[17];
    const float* lbn_g    = (const float*)d_in[18];
    const float* lbn_b    = (const float*)d_in[19];
    const float* fc2_W    = (const float*)d_in[20];
    const float* fc2_b    = (const float*)d_in[21];
    float* out = (float*)d_out;

    float *bufA, *bufB, *stats, *scalep, *shiftp, *xg, *m1, *m2;
    int *rowptr, *cursor;
    cudaGetSymbolAddress((void**)&bufA, g_bufA);
    cudaGetSymbolAddress((void**)&bufB, g_bufB);
    cudaGetSymbolAddress((void**)&stats, g_stats);
    cudaGetSymbolAddress((void**)&scalep, g_scale);
    cudaGetSymbolAddress((void**)&shiftp, g_shift);
    cudaGetSymbolAddress((void**)&xg, g_xg);
    cudaGetSymbolAddress((void**)&m1, g_m1);
    cudaGetSymbolAddress((void**)&m2, g_m2);
    cudaGetSymbolAddress((void**)&rowptr, g_rowptr);
    cudaGetSymbolAddress((void**)&cursor, g_cursor);

    cudaFuncSetAttribute(gemm64x128_kernel, cudaFuncAttributeMaxDynamicSharedMemorySize, 98304);

    const int WB = (NN * 32 + 255) / 256;   // warp-per-node grids
    const int EB = (EE + 255) / 256;
    const int GB = (NN + 63) / 64;
    const int SMEM = 98304;

    // ---- CSR build (once per launch; reused for all 5 layers) ----
    cudaMemsetAsync(rowptr, 0, (NN + 1) * sizeof(int));
    hist_kernel<<<EB, 256>>>(edst);
    scan_kernel<<<1, 1024>>>(rowptr, NN + 1);
    cudaMemsetAsync(cursor, 0, NN * sizeof(int));
    fill_kernel<<<EB, 256>>>(esrc, edst);

    // single upfront zero for all stats buffers
    cudaMemsetAsync(stats, 0, 8 * 1024 * sizeof(float));

    // ---- layer 0 ----
    agg0_kernel<<<WB, 256>>>(h);
    gemm64x128_kernel<<<GB, 256, SMEM>>>(bufA, W1, b1, 2.f, NN, 78, bufB, stats);
    finalize_kernel<<<1, 128>>>(stats, g1_gamma, g1_beta, 1.f / NN, 128, scalep, shiftp);

    // ---- layers 1..4 ----
    for (int l = 0; l < 4; ++l) {
        float* st = stats + (l + 1) * 1024;
        agg_kernel<<<WB, 256>>>(bufB, bufA, scalep, shiftp);
        gemm64x128_kernel<<<GB, 256, SMEM>>>(bufA, Wg + (size_t)l * 128 * 128, bg + l * 128,
                                             2.f, NN, 128, bufB, st);
        finalize_kernel<<<1, 128>>>(st, gg + l * 128, gb + l * 128, 1.f / NN, 128,
                                    scalep, shiftp);
    }

    // ---- graph sum readout ----
    cudaMemsetAsync(xg, 0, GG * 128 * sizeof(float));
    readout_kernel<<<WB, 256>>>(bufB, gid, scalep, shiftp);

    // ---- MLP head ----
    float* st5 = stats + 5 * 1024;
    float* st6 = stats + 6 * 1024;
    gemm_small_kernel<<<dim3(512 / 32, GG / 8), 256>>>(xg, fc1_W, fc1_b, GG, 128, 512, m1, st5);
    finalize_kernel<<<1, 512>>>(st5, bn1_g, bn1_b, 1.f / GG, 512, scalep, shiftp);
    norm_relu_kernel<<<(GG * 512 + 255) / 256, 256>>>(m1, scalep, shiftp, GG * 512, 512);

    gemm_small_kernel<<<dim3(256 / 32, GG / 8), 256>>>(m1, lin_W, lin_b, GG, 512, 256, m2, st6);
    finalize_kernel<<<1, 256>>>(st6, lbn_g, lbn_b, 1.f / GG, 256, scalep, shiftp);
    norm_relu_kernel<<<(GG * 256 + 255) / 256, 256>>>(m2, scalep, shiftp, GG * 256, 256);

    fc2_kernel<<<dim3(7, GG / 8), 256>>>(m2, fc2_W, fc2_b, out);
}

// round 4
// speedup vs baseline: 1.7298x; 1.7298x over previous
#include <cuda_runtime.h>
#include <cuda_bf16.h>
#include <math.h>
#include <stdint.h>

#define NN 100000
#define EE 1600000
#define GG 2048
#define NCOUT 204

// ---------------- static scratch (no runtime allocation allowed) ----------------
__device__ float g_bufA[NN * 128];       // t (GEMM input) per layer
__device__ float g_bufB[NN * 128];       // y (pre-BN GEMM output) per layer
__device__ int   g_rowptr[NN + 1];
__device__ int   g_cursor[NN];
__device__ int   g_col[EE];
__device__ float g_stats[8 * 1024];      // per-layer [sum(0..C) | sumsq(C..2C)]
__device__ float g_scale[512];
__device__ float g_shift[512];
__device__ float g_xg[GG * 128];
__device__ float g_m1[GG * 512];
__device__ float g_m2[GG * 256];
__device__ __nv_bfloat16 g_wthi[128 * 128];   // W^T split-high (n-major [n][k])
__device__ __nv_bfloat16 g_wtlo[128 * 128];   // W^T split-low

// ---------------- CSR build ----------------
__global__ void hist_kernel(const int* __restrict__ edst) {
    int e = blockIdx.x * blockDim.x + threadIdx.x;
    if (e < EE) atomicAdd(&g_rowptr[edst[e] + 1], 1);
}

// inclusive scan, single block of 1024, chunked (2 passes over data)
__global__ void scan_kernel(int* a, int n) {
    __shared__ int s[1024];
    int tid = threadIdx.x;
    int chunk = (n + 1023) >> 10;
    int beg = tid * chunk;
    int end = beg + chunk; if (end > n) end = n;
    int sum = 0;
    for (int i = beg; i < end; ++i) sum += a[i];
    s[tid] = sum;
    __syncthreads();
    for (int off = 1; off < 1024; off <<= 1) {
        int t = (tid >= off) ? s[tid - off] : 0;
        __syncthreads();
        s[tid] += t;
        __syncthreads();
    }
    int run = (tid > 0) ? s[tid - 1] : 0;
    for (int i = beg; i < end; ++i) { run += a[i]; a[i] = run; }
}

__global__ void fill_kernel(const int* __restrict__ esrc, const int* __restrict__ edst) {
    int e = blockIdx.x * blockDim.x + threadIdx.x;
    if (e >= EE) return;
    int d = edst[e];
    int pos = atomicAdd(&g_cursor[d], 1);
    g_col[g_rowptr[d] + pos] = esrc[e];
}

// ---------------- layer 0 aggregation: t = 2*h + sum_in(h), 78 dims ----------------
__global__ void agg0_kernel(const float* __restrict__ H) {
    int w = (blockIdx.x * blockDim.x + threadIdx.x) >> 5;
    if (w >= NN) return;
    int lid = threadIdx.x & 31;
    const float* hr = H + (size_t)w * 78;
    float a0 = 2.f * hr[lid];
    float a1 = 2.f * hr[lid + 32];
    float a2 = (lid < 14) ? 2.f * hr[lid + 64] : 0.f;
    int beg = g_rowptr[w], end = g_rowptr[w + 1];
    for (int j = beg; j < end; ++j) {
        int s = g_col[j];
        const float* hs = H + (size_t)s * 78;
        a0 += hs[lid];
        a1 += hs[lid + 32];
        if (lid < 14) a2 += hs[lid + 64];
    }
    float* t = g_bufA + (size_t)w * 128;
    t[lid] = a0;
    t[lid + 32] = a1;
    t[lid + 64] = (lid < 14) ? a2 : 0.f;
    t[lid + 96] = 0.f;   // zero-pad K 78..127 so GEMM padding is clean
}

// ---------------- mid-layer aggregation (128 dims), BN+ReLU fused on the read side --------
__global__ void agg_kernel(const float* __restrict__ Yin, float* __restrict__ Tout,
                           const float* __restrict__ scale, const float* __restrict__ shift) {
    int w = (blockIdx.x * blockDim.x + threadIdx.x) >> 5;
    if (w >= NN) return;
    int lid = threadIdx.x & 31;
    float4 sc = *(const float4*)&scale[lid * 4];
    float4 sh = *(const float4*)&shift[lid * 4];
    const float4* Y4 = (const float4*)Yin;
    float4 v = Y4[(size_t)w * 32 + lid];
    float a0 = 2.f * fmaxf(0.f, v.x * sc.x + sh.x);
    float a1 = 2.f * fmaxf(0.f, v.y * sc.y + sh.y);
    float a2 = 2.f * fmaxf(0.f, v.z * sc.z + sh.z);
    float a3 = 2.f * fmaxf(0.f, v.w * sc.w + sh.w);
    int beg = g_rowptr[w], end = g_rowptr[w + 1];
    for (int j = beg; j < end; ++j) {
        int s = g_col[j];
        float4 u = Y4[(size_t)s * 32 + lid];
        a0 += fmaxf(0.f, u.x * sc.x + sh.x);
        a1 += fmaxf(0.f, u.y * sc.y + sh.y);
        a2 += fmaxf(0.f, u.z * sc.z + sh.z);
        a3 += fmaxf(0.f, u.w * sc.w + sh.w);
    }
    float4 o = make_float4(a0, a1, a2, a3);
    ((float4*)Tout)[(size_t)w * 32 + lid] = o;
}

// ---------------- readout: xg[graph] += relu(bn(y[n])) ----------------
__global__ void readout_kernel(const float* __restrict__ Yin, const int* __restrict__ gid,
                               const float* __restrict__ scale, const float* __restrict__ shift) {
    int w = (blockIdx.x * blockDim.x + threadIdx.x) >> 5;
    if (w >= NN) return;
    int lid = threadIdx.x & 31;
    float4 sc = *(const float4*)&scale[lid * 4];
    float4 sh = *(const float4*)&shift[lid * 4];
    float4 v = ((const float4*)Yin)[(size_t)w * 32 + lid];
    int g = gid[w];
    float* dst = &g_xg[(size_t)g * 128 + lid * 4];
    atomicAdd(dst + 0, fmaxf(0.f, v.x * sc.x + sh.x));
    atomicAdd(dst + 1, fmaxf(0.f, v.y * sc.y + sh.y));
    atomicAdd(dst + 2, fmaxf(0.f, v.z * sc.z + sh.z));
    atomicAdd(dst + 3, fmaxf(0.f, v.w * sc.w + sh.w));
}

// ---------------- weight transpose + bf16 split (once per layer, tiny) ----------------
__global__ void wsplit_kernel(const float* __restrict__ W, int K,
                              __nv_bfloat16* __restrict__ Hi, __nv_bfloat16* __restrict__ Lo) {
    int i = blockIdx.x * blockDim.x + threadIdx.x;
    if (i >= 128 * 128) return;
    int k = i >> 7, n = i & 127;
    float w = (k < K) ? W[k * 128 + n] : 0.f;   // zero-pad K
    __nv_bfloat16 h = __float2bfloat16(w);
    Hi[n * 128 + k] = h;
    Lo[n * 128 + k] = __float2bfloat16(w - __bfloat162float(h));
}

// ---------------- HMMA helpers ----------------
__device__ __forceinline__ void mma16816(float c[4], uint32_t a0, uint32_t a1,
                                         uint32_t a2, uint32_t a3,
                                         uint32_t b0, uint32_t b1) {
    asm volatile(
        "mma.sync.aligned.m16n8k16.row.col.f32.bf16.bf16.f32 "
        "{%0,%1,%2,%3}, {%4,%5,%6,%7}, {%8,%9}, {%0,%1,%2,%3};"
        : "+f"(c[0]), "+f"(c[1]), "+f"(c[2]), "+f"(c[3])
        : "r"(a0), "r"(a1), "r"(a2), "r"(a3), "r"(b0), "r"(b1));
}

__device__ __forceinline__ uint32_t pack_bf16(float x, float y) {
    __nv_bfloat162 p;
    p.x = __float2bfloat16(x);
    p.y = __float2bfloat16(y);
    return *(uint32_t*)&p;
}

// ---------------- tensor GEMM: Y[rows,128] = T[rows,128] @ W[128,128] + bscale*b --------
// 128x128 CTA tile, 8 warps, mma.sync m16n8k16 bf16, 3-term split (th*wh+tl*wh+th*wl).
// K in 2 chunks of 64 (smem 75KB -> 2 CTAs/SM). Fused bias + BN stats.
#define PITCH 72
__global__ void __launch_bounds__(256, 2) gemm_mma_kernel(
    const float* __restrict__ T, const __nv_bfloat16* __restrict__ WtHi,
    const __nv_bfloat16* __restrict__ WtLo, const float* __restrict__ bias,
    float bscale, int rows, float* __restrict__ Y, float* __restrict__ stats) {
    extern __shared__ char smem[];
    __nv_bfloat16* Ah = (__nv_bfloat16*)smem;           // [128][72]
    __nv_bfloat16* Al = Ah + 128 * PITCH;
    __nv_bfloat16* Bh = Al + 128 * PITCH;
    __nv_bfloat16* Bl = Bh + 128 * PITCH;
    float* sbias = (float*)(Bl + 128 * PITCH);          // 128
    float* sstat = sbias + 128;                         // 256 (sum|sq)

    int tid = threadIdx.x;
    int lane = tid & 31, wid = tid >> 5;
    int q = lane & 3, rsel = lane >> 2;
    int m0 = wid * 16;
    int row0 = blockIdx.x * 128;

    if (tid < 128) sbias[tid] = bscale * bias[tid];
    sstat[tid] = 0.f;

    float acc[16][4];
#pragma unroll
    for (int nt = 0; nt < 16; ++nt)
#pragma unroll
        for (int j = 0; j < 4; ++j) acc[nt][j] = 0.f;

    for (int kc = 0; kc < 128; kc += 64) {
        // load + split A chunk [128 rows][64 k] fp32 -> bf16 hi/lo
        for (int idx = tid; idx < 2048; idx += 256) {
            int r = idx >> 4, c4 = idx & 15;
            int gr = row0 + r;
            float4 v = make_float4(0.f, 0.f, 0.f, 0.f);
            if (gr < rows) v = *(const float4*)&T[(size_t)gr * 128 + kc + c4 * 4];
            uint32_t h01 = pack_bf16(v.x, v.y), h23 = pack_bf16(v.z, v.w);
            __nv_bfloat162 hp0 = *(__nv_bfloat162*)&h01;
            __nv_bfloat162 hp1 = *(__nv_bfloat162*)&h23;
            uint32_t l01 = pack_bf16(v.x - __bfloat162float(hp0.x),
                                     v.y - __bfloat162float(hp0.y));
            uint32_t l23 = pack_bf16(v.z - __bfloat162float(hp1.x),
                                     v.w - __bfloat162float(hp1.y));
            uint2 hh = make_uint2(h01, h23), ll = make_uint2(l01, l23);
            *(uint2*)&Ah[r * PITCH + c4 * 4] = hh;
            *(uint2*)&Al[r * PITCH + c4 * 4] = ll;
        }
        // load B chunk [128 n][64 k] pre-split bf16
        for (int idx = tid; idx < 1024; idx += 256) {
            int r = idx >> 3, c8 = idx & 7;
            *(uint4*)&Bh[r * PITCH + c8 * 8] = *(const uint4*)&WtHi[r * 128 + kc + c8 * 8];
            *(uint4*)&Bl[r * PITCH + c8 * 8] = *(const uint4*)&WtLo[r * 128 + kc + c8 * 8];
        }
        __syncthreads();

#pragma unroll
        for (int term = 0; term < 3; ++term) {
            const __nv_bfloat16* Ab = (term == 1) ? Al : Ah;
            const __nv_bfloat16* Bb = (term == 2) ? Bl : Bh;
#pragma unroll
            for (int ks = 0; ks < 64; ks += 16) {
                const __nv_bfloat16* ar = Ab + (m0 + rsel) * PITCH + ks + 2 * q;
                uint32_t a0 = *(const uint32_t*)ar;
                uint32_t a1 = *(const uint32_t*)(ar + 8 * PITCH);
                uint32_t a2 = *(const uint32_t*)(ar + 8);
                uint32_t a3 = *(const uint32_t*)(ar + 8 * PITCH + 8);
#pragma unroll
                for (int nt = 0; nt < 16; ++nt) {
                    const __nv_bfloat16* br = Bb + (nt * 8 + rsel) * PITCH + ks + 2 * q;
                    uint32_t b0 = *(const uint32_t*)br;
                    uint32_t b1 = *(const uint32_t*)(br + 8);
                    mma16816(acc[nt], a0, a1, a2, a3, b0, b1);
                }
            }
        }
        __syncthreads();
    }

    // epilogue: bias, store, BN stats
    int r_lo = row0 + m0 + rsel, r_hi = r_lo + 8;
    bool vlo = r_lo < rows, vhi = r_hi < rows;
#pragma unroll
    for (int nt = 0; nt < 16; ++nt) {
        int c0 = nt * 8 + 2 * q;
        float b0 = sbias[c0], b1 = sbias[c0 + 1];
        float v00 = vlo ? acc[nt][0] + b0 : 0.f;
        float v01 = vlo ? acc[nt][1] + b1 : 0.f;
        float v10 = vhi ? acc[nt][2] + b0 : 0.f;
        float v11 = vhi ? acc[nt][3] + b1 : 0.f;
        if (vlo) *(float2*)&Y[(size_t)r_lo * 128 + c0] = make_float2(v00, v01);
        if (vhi) *(float2*)&Y[(size_t)r_hi * 128 + c0] = make_float2(v10, v11);
        float s0 = v00 + v10, s1 = v01 + v11;
        float q0 = v00 * v00 + v10 * v10, q1 = v01 * v01 + v11 * v11;
#pragma unroll
        for (int off = 4; off <= 16; off <<= 1) {
            s0 += __shfl_xor_sync(0xFFFFFFFFu, s0, off);
            s1 += __shfl_xor_sync(0xFFFFFFFFu, s1, off);
            q0 += __shfl_xor_sync(0xFFFFFFFFu, q0, off);
            q1 += __shfl_xor_sync(0xFFFFFFFFu, q1, off);
        }
        if (rsel == 0) {
            atomicAdd(&sstat[c0], s0);
            atomicAdd(&sstat[c0 + 1], s1);
            atomicAdd(&sstat[128 + c0], q0);
            atomicAdd(&sstat[128 + c0 + 1], q1);
        }
    }
    __syncthreads();
    atomicAdd(&stats[tid], sstat[tid]);
}

// ---------------- BN coefficient finalize ----------------
__global__ void finalize_kernel(const float* __restrict__ stats, const float* __restrict__ gamma,
                                const float* __restrict__ beta, float invn, int C,
                                float* __restrict__ scale, float* __restrict__ shift) {
    int c = blockIdx.x * blockDim.x + threadIdx.x;
    if (c >= C) return;
    float mu = stats[c] * invn;
    float var = stats[C + c] * invn - mu * mu;
    float inv = rsqrtf(var + 1e-5f);
    float s = gamma[c] * inv;
    scale[c] = s;
    shift[c] = beta[c] - mu * s;
}

// ---------------- small MLP GEMM (thread-per-output) ----------------
__global__ void gemm_small_kernel(const float* __restrict__ X, const float* __restrict__ W,
                                  const float* __restrict__ bias, int R, int K, int C,
                                  float* __restrict__ Y, float* __restrict__ stats) {
    int c = blockIdx.x * 32 + (threadIdx.x & 31);
    int r = blockIdx.y * 8 + (threadIdx.x >> 5);
    if (c >= C || r >= R) return;
    float acc = bias[c];
    const float* xr = X + (size_t)r * K;
    for (int k = 0; k < K; ++k) acc = fmaf(xr[k], W[(size_t)k * C + c], acc);
    Y[(size_t)r * C + c] = acc;
    atomicAdd(&stats[c], acc);
    atomicAdd(&stats[C + c], acc * acc);
}

__global__ void norm_relu_kernel(float* __restrict__ Y, const float* __restrict__ scale,
                                 const float* __restrict__ shift, int total, int C) {
    int i = blockIdx.x * blockDim.x + threadIdx.x;
    if (i >= total) return;
    int c = i % C;
    float v = Y[i] * scale[c] + shift[c];
    Y[i] = fmaxf(v, 0.f);
}

__global__ void fc2_kernel(const float* __restrict__ X, const float* __restrict__ W,
                           const float* __restrict__ bias, float* __restrict__ out) {
    int c = blockIdx.x * 32 + (threadIdx.x & 31);
    int g = blockIdx.y * 8 + (threadIdx.x >> 5);
    if (c >= NCOUT || g >= GG) return;
    float acc = bias[204 + c];
    const float* xr = X + (size_t)g * 256;
    for (int k = 0; k < 256; ++k) acc = fmaf(xr[k], W[(size_t)k * 408 + 204 + c], acc);
    out[(size_t)g * NCOUT + c] = 1.f / (1.f + expf(-acc));
}

// ---------------- host orchestration ----------------
extern "C" void kernel_launch(void* const* d_in, const int* in_sizes, int n_in,
                              void* d_out, int out_size) {
    const float* h        = (const float*)d_in[0];
    const int*   esrc     = (const int*)d_in[1];
    const int*   edst     = (const int*)d_in[2];
    const int*   gid      = (const int*)d_in[3];
    const float* W1       = (const float*)d_in[4];
    const float* b1       = (const float*)d_in[5];
    const float* g1_gamma = (const float*)d_in[6];
    const float* g1_beta  = (const float*)d_in[7];
    const float* Wg       = (const float*)d_in[8];
    const float* bg       = (const float*)d_in[9];
    const float* gg       = (const float*)d_in[10];
    const float* gb       = (const float*)d_in[11];
    const float* fc1_W    = (const float*)d_in[12];
    const float* fc1_b    = (const float*)d_in[13];
    const float* bn1_g    = (const float*)d_in[14];
    const float* bn1_b    = (const float*)d_in[15];
    const float* lin_W    = (const float*)d_in[16];
    const float* lin_b    = (const float*)d_in[17];
    const float* lbn_g    = (const float*)d_in[18];
    const float* lbn_b    = (const float*)d_in[19];
    const float* fc2_W    = (const float*)d_in[20];
    const float* fc2_b    = (const float*)d_in[21];
    float* out = (float*)d_out;

    float *bufA, *bufB, *stats, *scalep, *shiftp, *xg, *m1, *m2;
    int *rowptr, *cursor;
    __nv_bfloat16 *wthi, *wtlo;
    cudaGetSymbolAddress((void**)&bufA, g_bufA);
    cudaGetSymbolAddress((void**)&bufB, g_bufB);
    cudaGetSymbolAddress((void**)&stats, g_stats);
    cudaGetSymbolAddress((void**)&scalep, g_scale);
    cudaGetSymbolAddress((void**)&shiftp, g_shift);
    cudaGetSymbolAddress((void**)&xg, g_xg);
    cudaGetSymbolAddress((void**)&m1, g_m1);
    cudaGetSymbolAddress((void**)&m2, g_m2);
    cudaGetSymbolAddress((void**)&rowptr, g_rowptr);
    cudaGetSymbolAddress((void**)&cursor, g_cursor);
    cudaGetSymbolAddress((void**)&wthi, g_wthi);
    cudaGetSymbolAddress((void**)&wtlo, g_wtlo);

    const int SMEMMA = 4 * 128 * PITCH * 2 + 128 * 4 + 256 * 4;   // 75264
    cudaFuncSetAttribute(gemm_mma_kernel, cudaFuncAttributeMaxDynamicSharedMemorySize, SMEMMA);

    const int WB = (NN * 32 + 255) / 256;   // warp-per-node grids
    const int EB = (EE + 255) / 256;
    const int GBt = (NN + 127) / 128;       // 782 GEMM tiles

    // ---- CSR build (once per launch; reused for all 5 layers) ----
    cudaMemsetAsync(rowptr, 0, (NN + 1) * sizeof(int));
    hist_kernel<<<EB, 256>>>(edst);
    scan_kernel<<<1, 1024>>>(rowptr, NN + 1);
    cudaMemsetAsync(cursor, 0, NN * sizeof(int));
    fill_kernel<<<EB, 256>>>(esrc, edst);

    // single upfront zero for all stats buffers
    cudaMemsetAsync(stats, 0, 8 * 1024 * sizeof(float));

    // ---- layer 0 ----
    agg0_kernel<<<WB, 256>>>(h);
    wsplit_kernel<<<64, 256>>>(W1, 78, wthi, wtlo);
    gemm_mma_kernel<<<GBt, 256, SMEMMA>>>(bufA, wthi, wtlo, b1, 2.f, NN, bufB, stats);
    finalize_kernel<<<1, 128>>>(stats, g1_gamma, g1_beta, 1.f / NN, 128, scalep, shiftp);

    // ---- layers 1..4 ----
    for (int l = 0; l < 4; ++l) {
        float* st = stats + (l + 1) * 1024;
        agg_kernel<<<WB, 256>>>(bufB, bufA, scalep, shiftp);
        wsplit_kernel<<<64, 256>>>(Wg + (size_t)l * 128 * 128, 128, wthi, wtlo);
        gemm_mma_kernel<<<GBt, 256, SMEMMA>>>(bufA, wthi, wtlo, bg + l * 128, 2.f, NN, bufB, st);
        finalize_kernel<<<1, 128>>>(st, gg + l * 128, gb + l * 128, 1.f / NN, 128,
                                    scalep, shiftp);
    }

    // ---- graph sum readout ----
    cudaMemsetAsync(xg, 0, GG * 128 * sizeof(float));
    readout_kernel<<<WB, 256>>>(bufB, gid, scalep, shiftp);

    // ---- MLP head ----
    float* st5 = stats + 5 * 1024;
    float* st6 = stats + 6 * 1024;
    gemm_small_kernel<<<dim3(512 / 32, GG / 8), 256>>>(xg, fc1_W, fc1_b, GG, 128, 512, m1, st5);
    finalize_kernel<<<1, 512>>>(st5, bn1_g, bn1_b, 1.f / GG, 512, scalep, shiftp);
    norm_relu_kernel<<<(GG * 512 + 255) / 256, 256>>>(m1, scalep, shiftp, GG * 512, 512);

    gemm_small_kernel<<<dim3(256 / 32, GG / 8), 256>>>(m1, lin_W, lin_b, GG, 512, 256, m2, st6);
    finalize_kernel<<<1, 256>>>(st6, lbn_g, lbn_b, 1.f / GG, 256, scalep, shiftp);
    norm_relu_kernel<<<(GG * 256 + 255) / 256, 256>>>(m2, scalep, shiftp, GG * 256, 256);

    fc2_kernel<<<dim3(7, GG / 8), 256>>>(m2, fc2_W, fc2_b, out);
}

// round 5
// speedup vs baseline: 1.7795x; 1.0287x over previous
#include <cuda_runtime.h>
#include <cuda_bf16.h>
#include <cuda_fp16.h>
#include <math.h>
#include <stdint.h>

#define NN 100000
#define EE 1600000
#define GG 2048
#define NCOUT 204

// ---------------- static scratch (no runtime allocation allowed) ----------------
__device__ float  g_bufA[NN * 128];      // t (GEMM input, fp32) per layer
__device__ __half g_bufY[NN * 128];      // y (pre-BN GEMM output, fp16) per layer
__device__ int    g_rowptr[NN + 1];
__device__ int    g_cursor[NN];
__device__ int    g_col[EE];
__device__ float  g_stats[8 * 1024];     // per-layer [sum(0..C) | sumsq(C..2C)]
__device__ float  g_xg[GG * 128];
__device__ float  g_m1[GG * 512];
__device__ float  g_m2[GG * 256];
__device__ __nv_bfloat16 g_wthi[128 * 128];   // W^T split-high (n-major [n][k])
__device__ __nv_bfloat16 g_wtlo[128 * 128];   // W^T split-low

// ---------------- CSR build ----------------
__global__ void hist_kernel(const int* __restrict__ edst) {
    int e = blockIdx.x * blockDim.x + threadIdx.x;
    if (e < EE) atomicAdd(&g_rowptr[edst[e] + 1], 1);
}

// inclusive scan, single block of 1024, chunked (2 passes over data)
__global__ void scan_kernel(int* a, int n) {
    __shared__ int s[1024];
    int tid = threadIdx.x;
    int chunk = (n + 1023) >> 10;
    int beg = tid * chunk;
    int end = beg + chunk; if (end > n) end = n;
    int sum = 0;
    for (int i = beg; i < end; ++i) sum += a[i];
    s[tid] = sum;
    __syncthreads();
    for (int off = 1; off < 1024; off <<= 1) {
        int t = (tid >= off) ? s[tid - off] : 0;
        __syncthreads();
        s[tid] += t;
        __syncthreads();
    }
    int run = (tid > 0) ? s[tid - 1] : 0;
    for (int i = beg; i < end; ++i) { run += a[i]; a[i] = run; }
}

__global__ void fill_kernel(const int* __restrict__ esrc, const int* __restrict__ edst) {
    int e = blockIdx.x * blockDim.x + threadIdx.x;
    if (e >= EE) return;
    int d = edst[e];
    int pos = atomicAdd(&g_cursor[d], 1);
    g_col[g_rowptr[d] + pos] = esrc[e];
}

// ---------------- layer 0 aggregation: t = 2*h + sum_in(h), 78 dims ----------------
__global__ void agg0_kernel(const float* __restrict__ H) {
    int w = (blockIdx.x * blockDim.x + threadIdx.x) >> 5;
    if (w >= NN) return;
    int lid = threadIdx.x & 31;
    const float* hr = H + (size_t)w * 78;
    float a0 = 2.f * hr[lid];
    float a1 = 2.f * hr[lid + 32];
    float a2 = (lid < 14) ? 2.f * hr[lid + 64] : 0.f;
    int beg = g_rowptr[w], end = g_rowptr[w + 1];
    int j = beg;
    for (; j + 2 <= end; j += 2) {
        int s0 = g_col[j], s1 = g_col[j + 1];
        const float* h0 = H + (size_t)s0 * 78;
        const float* h1 = H + (size_t)s1 * 78;
        float x0 = h0[lid], y0 = h0[lid + 32];
        float x1 = h1[lid], y1 = h1[lid + 32];
        float z0 = (lid < 14) ? h0[lid + 64] : 0.f;
        float z1 = (lid < 14) ? h1[lid + 64] : 0.f;
        a0 += x0 + x1; a1 += y0 + y1; a2 += z0 + z1;
    }
    if (j < end) {
        const float* hs = H + (size_t)g_col[j] * 78;
        a0 += hs[lid];
        a1 += hs[lid + 32];
        if (lid < 14) a2 += hs[lid + 64];
    }
    float* t = g_bufA + (size_t)w * 128;
    t[lid] = a0;
    t[lid + 32] = a1;
    t[lid + 64] = (lid < 14) ? a2 : 0.f;
    t[lid + 96] = 0.f;   // zero-pad K 78..127 so GEMM padding is clean
}

// ---------------- mid-layer aggregation (128 dims, fp16 gather) ---------------------------
// BN scale/shift recomputed per CTA from raw stats (kills finalize launches).
// x = relu(y*sc+sh); t[n] = 2*x[n] + sum_{src} x[src]
__global__ void agg_kernel(const __half* __restrict__ Yin, float* __restrict__ Tout,
                           const float* __restrict__ stats, const float* __restrict__ gamma,
                           const float* __restrict__ beta) {
    __shared__ float ssc[128], ssh[128];
    int tid = threadIdx.x;
    if (tid < 128) {
        const float invn = 1.f / NN;
        float mu = stats[tid] * invn;
        float var = stats[128 + tid] * invn - mu * mu;
        float s = gamma[tid] * rsqrtf(var + 1e-5f);
        ssc[tid] = s;
        ssh[tid] = beta[tid] - mu * s;
    }
    __syncthreads();

    int w = (blockIdx.x * blockDim.x + tid) >> 5;
    if (w >= NN) return;
    int lid = tid & 31;
    float4 sc = *(const float4*)&ssc[lid * 4];
    float4 sh = *(const float4*)&ssh[lid * 4];
    const uint2* Y2 = (const uint2*)Yin;   // 4 halves per uint2, 32 uint2 per row

    uint2 raw = Y2[(size_t)w * 32 + lid];
    float2 f0 = __half22float2(*(__half2*)&raw.x);
    float2 f1 = __half22float2(*(__half2*)&raw.y);
    float a0 = 2.f * fmaxf(0.f, f0.x * sc.x + sh.x);
    float a1 = 2.f * fmaxf(0.f, f0.y * sc.y + sh.y);
    float a2 = 2.f * fmaxf(0.f, f1.x * sc.z + sh.z);
    float a3 = 2.f * fmaxf(0.f, f1.y * sc.w + sh.w);

    int beg = g_rowptr[w], end = g_rowptr[w + 1];
    int j = beg;
    for (; j + 2 <= end; j += 2) {
        int s0 = g_col[j], s1 = g_col[j + 1];
        uint2 r0 = Y2[(size_t)s0 * 32 + lid];
        uint2 r1 = Y2[(size_t)s1 * 32 + lid];
        float2 u0 = __half22float2(*(__half2*)&r0.x);
        float2 u1 = __half22float2(*(__half2*)&r0.y);
        float2 v0 = __half22float2(*(__half2*)&r1.x);
        float2 v1 = __half22float2(*(__half2*)&r1.y);
        a0 += fmaxf(0.f, u0.x * sc.x + sh.x) + fmaxf(0.f, v0.x * sc.x + sh.x);
        a1 += fmaxf(0.f, u0.y * sc.y + sh.y) + fmaxf(0.f, v0.y * sc.y + sh.y);
        a2 += fmaxf(0.f, u1.x * sc.z + sh.z) + fmaxf(0.f, v1.x * sc.z + sh.z);
        a3 += fmaxf(0.f, u1.y * sc.w + sh.w) + fmaxf(0.f, v1.y * sc.w + sh.w);
    }
    if (j < end) {
        uint2 r0 = Y2[(size_t)g_col[j] * 32 + lid];
        float2 u0 = __half22float2(*(__half2*)&r0.x);
        float2 u1 = __half22float2(*(__half2*)&r0.y);
        a0 += fmaxf(0.f, u0.x * sc.x + sh.x);
        a1 += fmaxf(0.f, u0.y * sc.y + sh.y);
        a2 += fmaxf(0.f, u1.x * sc.z + sh.z);
        a3 += fmaxf(0.f, u1.y * sc.w + sh.w);
    }
    ((float4*)Tout)[(size_t)w * 32 + lid] = make_float4(a0, a1, a2, a3);
}

// ---------------- readout: xg[graph] += relu(bn(y[n])) (fp16 y) ----------------
__global__ void readout_kernel(const __half* __restrict__ Yin, const int* __restrict__ gid,
                               const float* __restrict__ stats, const float* __restrict__ gamma,
                               const float* __restrict__ beta) {
    __shared__ float ssc[128], ssh[128];
    int tid = threadIdx.x;
    if (tid < 128) {
        const float invn = 1.f / NN;
        float mu = stats[tid] * invn;
        float var = stats[128 + tid] * invn - mu * mu;
        float s = gamma[tid] * rsqrtf(var + 1e-5f);
        ssc[tid] = s;
        ssh[tid] = beta[tid] - mu * s;
    }
    __syncthreads();
    int w = (blockIdx.x * blockDim.x + tid) >> 5;
    if (w >= NN) return;
    int lid = tid & 31;
    float4 sc = *(const float4*)&ssc[lid * 4];
    float4 sh = *(const float4*)&ssh[lid * 4];
    uint2 raw = ((const uint2*)Yin)[(size_t)w * 32 + lid];
    float2 f0 = __half22float2(*(__half2*)&raw.x);
    float2 f1 = __half22float2(*(__half2*)&raw.y);
    int g = gid[w];
    float* dst = &g_xg[(size_t)g * 128 + lid * 4];
    atomicAdd(dst + 0, fmaxf(0.f, f0.x * sc.x + sh.x));
    atomicAdd(dst + 1, fmaxf(0.f, f0.y * sc.y + sh.y));
    atomicAdd(dst + 2, fmaxf(0.f, f1.x * sc.z + sh.z));
    atomicAdd(dst + 3, fmaxf(0.f, f1.y * sc.w + sh.w));
}

// ---------------- weight transpose + bf16 split (once per layer, tiny) ----------------
__global__ void wsplit_kernel(const float* __restrict__ W, int K,
                              __nv_bfloat16* __restrict__ Hi, __nv_bfloat16* __restrict__ Lo) {
    int i = blockIdx.x * blockDim.x + threadIdx.x;
    if (i >= 128 * 128) return;
    int k = i >> 7, n = i & 127;
    float w = (k < K) ? W[k * 128 + n] : 0.f;   // zero-pad K
    __nv_bfloat16 h = __float2bfloat16(w);
    Hi[n * 128 + k] = h;
    Lo[n * 128 + k] = __float2bfloat16(w - __bfloat162float(h));
}

// ---------------- HMMA helpers ----------------
__device__ __forceinline__ void mma16816(float c[4], uint32_t a0, uint32_t a1,
                                         uint32_t a2, uint32_t a3,
                                         uint32_t b0, uint32_t b1) {
    asm volatile(
        "mma.sync.aligned.m16n8k16.row.col.f32.bf16.bf16.f32 "
        "{%0,%1,%2,%3}, {%4,%5,%6,%7}, {%8,%9}, {%0,%1,%2,%3};"
        : "+f"(c[0]), "+f"(c[1]), "+f"(c[2]), "+f"(c[3])
        : "r"(a0), "r"(a1), "r"(a2), "r"(a3), "r"(b0), "r"(b1));
}

__device__ __forceinline__ uint32_t pack_bf16(float x, float y) {
    __nv_bfloat162 p;
    p.x = __float2bfloat16(x);
    p.y = __float2bfloat16(y);
    return *(uint32_t*)&p;
}

// ---------------- tensor GEMM: y[rows,128] = T[rows,128] @ W[128,128] + bscale*b --------
// 128x128 CTA tile, 8 warps, mma.sync m16n8k16 bf16, 3-term split (th*wh+tl*wh+th*wl).
// K in 2 chunks of 64 (smem 75KB -> 2 CTAs/SM). Fused bias + BN stats; y stored fp16
// (stats computed from exact fp32 values before the rounding).
#define PITCH 72
__global__ void __launch_bounds__(256, 2) gemm_mma_kernel(
    const float* __restrict__ T, const __nv_bfloat16* __restrict__ WtHi,
    const __nv_bfloat16* __restrict__ WtLo, const float* __restrict__ bias,
    float bscale, int rows, __half* __restrict__ Y, float* __restrict__ stats) {
    extern __shared__ char smem[];
    __nv_bfloat16* Ah = (__nv_bfloat16*)smem;           // [128][72]
    __nv_bfloat16* Al = Ah + 128 * PITCH;
    __nv_bfloat16* Bh = Al + 128 * PITCH;
    __nv_bfloat16* Bl = Bh + 128 * PITCH;
    float* sbias = (float*)(Bl + 128 * PITCH);          // 128
    float* sstat = sbias + 128;                         // 256 (sum|sq)

    int tid = threadIdx.x;
    int lane = tid & 31, wid = tid >> 5;
    int q = lane & 3, rsel = lane >> 2;
    int m0 = wid * 16;
    int row0 = blockIdx.x * 128;

    if (tid < 128) sbias[tid] = bscale * bias[tid];
    sstat[tid] = 0.f;

    float acc[16][4];
#pragma unroll
    for (int nt = 0; nt < 16; ++nt)
#pragma unroll
        for (int j = 0; j < 4; ++j) acc[nt][j] = 0.f;

    for (int kc = 0; kc < 128; kc += 64) {
        // load + split A chunk [128 rows][64 k] fp32 -> bf16 hi/lo
        for (int idx = tid; idx < 2048; idx += 256) {
            int r = idx >> 4, c4 = idx & 15;
            int gr = row0 + r;
            float4 v = make_float4(0.f, 0.f, 0.f, 0.f);
            if (gr < rows) v = *(const float4*)&T[(size_t)gr * 128 + kc + c4 * 4];
            uint32_t h01 = pack_bf16(v.x, v.y), h23 = pack_bf16(v.z, v.w);
            __nv_bfloat162 hp0 = *(__nv_bfloat162*)&h01;
            __nv_bfloat162 hp1 = *(__nv_bfloat162*)&h23;
            uint32_t l01 = pack_bf16(v.x - __bfloat162float(hp0.x),
                                     v.y - __bfloat162float(hp0.y));
            uint32_t l23 = pack_bf16(v.z - __bfloat162float(hp1.x),
                                     v.w - __bfloat162float(hp1.y));
            uint2 hh = make_uint2(h01, h23), ll = make_uint2(l01, l23);
            *(uint2*)&Ah[r * PITCH + c4 * 4] = hh;
            *(uint2*)&Al[r * PITCH + c4 * 4] = ll;
        }
        // load B chunk [128 n][64 k] pre-split bf16
        for (int idx = tid; idx < 1024; idx += 256) {
            int r = idx >> 3, c8 = idx & 7;
            *(uint4*)&Bh[r * PITCH + c8 * 8] = *(const uint4*)&WtHi[r * 128 + kc + c8 * 8];
            *(uint4*)&Bl[r * PITCH + c8 * 8] = *(const uint4*)&WtLo[r * 128 + kc + c8 * 8];
        }
        __syncthreads();

#pragma unroll
        for (int term = 0; term < 3; ++term) {
            const __nv_bfloat16* Ab = (term == 1) ? Al : Ah;
            const __nv_bfloat16* Bb = (term == 2) ? Bl : Bh;
#pragma unroll
            for (int ks = 0; ks < 64; ks += 16) {
                const __nv_bfloat16* ar = Ab + (m0 + rsel) * PITCH + ks + 2 * q;
                uint32_t a0 = *(const uint32_t*)ar;
                uint32_t a1 = *(const uint32_t*)(ar + 8 * PITCH);
                uint32_t a2 = *(const uint32_t*)(ar + 8);
                uint32_t a3 = *(const uint32_t*)(ar + 8 * PITCH + 8);
#pragma unroll
                for (int nt = 0; nt < 16; ++nt) {
                    const __nv_bfloat16* br = Bb + (nt * 8 + rsel) * PITCH + ks + 2 * q;
                    uint32_t b0 = *(const uint32_t*)br;
                    uint32_t b1 = *(const uint32_t*)(br + 8);
                    mma16816(acc[nt], a0, a1, a2, a3, b0, b1);
                }
            }
        }
        __syncthreads();
    }

    // epilogue: bias, fp16 store, BN stats (from exact fp32 values)
    int r_lo = row0 + m0 + rsel, r_hi = r_lo + 8;
    bool vlo = r_lo < rows, vhi = r_hi < rows;
#pragma unroll
    for (int nt = 0; nt < 16; ++nt) {
        int c0 = nt * 8 + 2 * q;
        float b0 = sbias[c0], b1 = sbias[c0 + 1];
        float v00 = vlo ? acc[nt][0] + b0 : 0.f;
        float v01 = vlo ? acc[nt][1] + b1 : 0.f;
        float v10 = vhi ? acc[nt][2] + b0 : 0.f;
        float v11 = vhi ? acc[nt][3] + b1 : 0.f;
        if (vlo) *(__half2*)&Y[(size_t)r_lo * 128 + c0] = __floats2half2_rn(v00, v01);
        if (vhi) *(__half2*)&Y[(size_t)r_hi * 128 + c0] = __floats2half2_rn(v10, v11);
        float s0 = v00 + v10, s1 = v01 + v11;
        float q0 = v00 * v00 + v10 * v10, q1 = v01 * v01 + v11 * v11;
#pragma unroll
        for (int off = 4; off <= 16; off <<= 1) {
            s0 += __shfl_xor_sync(0xFFFFFFFFu, s0, off);
            s1 += __shfl_xor_sync(0xFFFFFFFFu, s1, off);
            q0 += __shfl_xor_sync(0xFFFFFFFFu, q0, off);
            q1 += __shfl_xor_sync(0xFFFFFFFFu, q1, off);
        }
        if (rsel == 0) {
            atomicAdd(&sstat[c0], s0);
            atomicAdd(&sstat[c0 + 1], s1);
            atomicAdd(&sstat[128 + c0], q0);
            atomicAdd(&sstat[128 + c0 + 1], q1);
        }
    }
    __syncthreads();
    atomicAdd(&stats[tid], sstat[tid]);
}

// ---------------- small MLP GEMM (thread-per-output) ----------------
__global__ void gemm_small_kernel(const float* __restrict__ X, const float* __restrict__ W,
                                  const float* __restrict__ bias, int R, int K, int C,
                                  float* __restrict__ Y, float* __restrict__ stats) {
    int c = blockIdx.x * 32 + (threadIdx.x & 31);
    int r = blockIdx.y * 8 + (threadIdx.x >> 5);
    if (c >= C || r >= R) return;
    float acc = bias[c];
    const float* xr = X + (size_t)r * K;
    for (int k = 0; k < K; ++k) acc = fmaf(xr[k], W[(size_t)k * C + c], acc);
    Y[(size_t)r * C + c] = acc;
    atomicAdd(&stats[c], acc);
    atomicAdd(&stats[C + c], acc * acc);
}

// norm+relu with BN finalize folded in (stats -> scale/shift per element)
__global__ void norm_relu_kernel(float* __restrict__ Y, const float* __restrict__ stats,
                                 const float* __restrict__ gamma, const float* __restrict__ beta,
                                 float invn, int total, int C) {
    int i = blockIdx.x * blockDim.x + threadIdx.x;
    if (i >= total) return;
    int c = i % C;
    float mu = stats[c] * invn;
    float var = stats[C + c] * invn - mu * mu;
    float s = gamma[c] * rsqrtf(var + 1e-5f);
    float v = (Y[i] - mu) * s + beta[c];
    Y[i] = fmaxf(v, 0.f);
}

__global__ void fc2_kernel(const float* __restrict__ X, const float* __restrict__ W,
                           const float* __restrict__ bias, float* __restrict__ out) {
    int c = blockIdx.x * 32 + (threadIdx.x & 31);
    int g = blockIdx.y * 8 + (threadIdx.x >> 5);
    if (c >= NCOUT || g >= GG) return;
    float acc = bias[204 + c];
    const float* xr = X + (size_t)g * 256;
    for (int k = 0; k < 256; ++k) acc = fmaf(xr[k], W[(size_t)k * 408 + 204 + c], acc);
    out[(size_t)g * NCOUT + c] = 1.f / (1.f + expf(-acc));
}

// ---------------- host orchestration ----------------
extern "C" void kernel_launch(void* const* d_in, const int* in_sizes, int n_in,
                              void* d_out, int out_size) {
    const float* h        = (const float*)d_in[0];
    const int*   esrc     = (const int*)d_in[1];
    const int*   edst     = (const int*)d_in[2];
    const int*   gid      = (const int*)d_in[3];
    const float* W1       = (const float*)d_in[4];
    const float* b1       = (const float*)d_in[5];
    const float* g1_gamma = (const float*)d_in[6];
    const float* g1_beta  = (const float*)d_in[7];
    const float* Wg       = (const float*)d_in[8];
    const float* bg       = (const float*)d_in[9];
    const float* gg       = (const float*)d_in[10];
    const float* gb       = (const float*)d_in[11];
    const float* fc1_W    = (const float*)d_in[12];
    const float* fc1_b    = (const float*)d_in[13];
    const float* bn1_g    = (const float*)d_in[14];
    const float* bn1_b    = (const float*)d_in[15];
    const float* lin_W    = (const float*)d_in[16];
    const float* lin_b    = (const float*)d_in[17];
    const float* lbn_g    = (const float*)d_in[18];
    const float* lbn_b    = (const float*)d_in[19];
    const float* fc2_W    = (const float*)d_in[20];
    const float* fc2_b    = (const float*)d_in[21];
    float* out = (float*)d_out;

    float *bufA, *stats, *xg, *m1, *m2;
    __half* bufY;
    int *rowptr, *cursor;
    __nv_bfloat16 *wthi, *wtlo;
    cudaGetSymbolAddress((void**)&bufA, g_bufA);
    cudaGetSymbolAddress((void**)&bufY, g_bufY);
    cudaGetSymbolAddress((void**)&stats, g_stats);
    cudaGetSymbolAddress((void**)&xg, g_xg);
    cudaGetSymbolAddress((void**)&m1, g_m1);
    cudaGetSymbolAddress((void**)&m2, g_m2);
    cudaGetSymbolAddress((void**)&rowptr, g_rowptr);
    cudaGetSymbolAddress((void**)&cursor, g_cursor);
    cudaGetSymbolAddress((void**)&wthi, g_wthi);
    cudaGetSymbolAddress((void**)&wtlo, g_wtlo);

    const int SMEMMA = 4 * 128 * PITCH * 2 + 128 * 4 + 256 * 4;   // 75264
    cudaFuncSetAttribute(gemm_mma_kernel, cudaFuncAttributeMaxDynamicSharedMemorySize, SMEMMA);

    const int WB = (NN * 32 + 255) / 256;   // warp-per-node grids
    const int EB = (EE + 255) / 256;
    const int GBt = (NN + 127) / 128;       // 782 GEMM tiles

    // ---- CSR build (once per launch; reused for all 5 layers) ----
    cudaMemsetAsync(rowptr, 0, (NN + 1) * sizeof(int));
    hist_kernel<<<EB, 256>>>(edst);
    scan_kernel<<<1, 1024>>>(rowptr, NN + 1);
    cudaMemsetAsync(cursor, 0, NN * sizeof(int));
    fill_kernel<<<EB, 256>>>(esrc, edst);

    // single upfront zero for all stats buffers + xg
    cudaMemsetAsync(stats, 0, 8 * 1024 * sizeof(float));
    cudaMemsetAsync(xg, 0, GG * 128 * sizeof(float));

    // ---- layer 0 ----
    agg0_kernel<<<WB, 256>>>(h);
    wsplit_kernel<<<64, 256>>>(W1, 78, wthi, wtlo);
    gemm_mma_kernel<<<GBt, 256, SMEMMA>>>(bufA, wthi, wtlo, b1, 2.f, NN, bufY, stats);

    // ---- layers 1..4 (BN of layer l-1 fused into agg read) ----
    const float* gmas[5] = {g1_gamma, gg, gg + 128, gg + 256, gg + 384};
    const float* btas[5] = {g1_beta,  gb, gb + 128, gb + 256, gb + 384};
    for (int l = 0; l < 4; ++l) {
        float* stPrev = stats + l * 1024;
        float* st = stats + (l + 1) * 1024;
        agg_kernel<<<WB, 256>>>(bufY, bufA, stPrev, gmas[l], btas[l]);
        wsplit_kernel<<<64, 256>>>(Wg + (size_t)l * 128 * 128, 128, wthi, wtlo);
        gemm_mma_kernel<<<GBt, 256, SMEMMA>>>(bufA, wthi, wtlo, bg + l * 128, 2.f, NN, bufY, st);
    }

    // ---- graph sum readout (BN of layer 4 fused) ----
    readout_kernel<<<WB, 256>>>(bufY, gid, stats + 4 * 1024, gmas[4], btas[4]);

    // ---- MLP head ----
    float* st5 = stats + 5 * 1024;
    float* st6 = stats + 6 * 1024;
    gemm_small_kernel<<<dim3(512 / 32, GG / 8), 256>>>(xg, fc1_W, fc1_b, GG, 128, 512, m1, st5);
    norm_relu_kernel<<<(GG * 512 + 255) / 256, 256>>>(m1, st5, bn1_g, bn1_b, 1.f / GG,
                                                      GG * 512, 512);

    gemm_small_kernel<<<dim3(256 / 32, GG / 8), 256>>>(m1, lin_W, lin_b, GG, 512, 256, m2, st6);
    norm_relu_kernel<<<(GG * 256 + 255) / 256, 256>>>(m2, st6, lbn_g, lbn_b, 1.f / GG,
                                                      GG * 256, 256);

    fc2_kernel<<<dim3(7, GG / 8), 256>>>(m2, fc2_W, fc2_b, out);
}

// round 6
// speedup vs baseline: 1.7805x; 1.0006x over previous
#include <cuda_runtime.h>
#include <cuda_bf16.h>
#include <cuda_fp16.h>
#include <math.h>
#include <stdint.h>

#define NN 100000
#define EE 1600000
#define GG 2048
#define NCOUT 204

// ---------------- static scratch (no runtime allocation allowed) ----------------
__device__ float  g_bufA[NN * 128];      // t (GEMM input, fp32) per layer
__device__ __half g_bufY[NN * 128];      // y (pre-BN GEMM output, fp16)
__device__ __half g_bufX[NN * 128];      // x = relu(bn(y)) (fp16)
__device__ int    g_rowptr[NN + 1];
__device__ int    g_cursor[NN];
__device__ int    g_col[EE];
__device__ float  g_stats[8 * 1024];     // per-layer [sum(0..C) | sumsq(C..2C)]
__device__ float  g_xg[GG * 128];
__device__ float  g_m1[GG * 512];
__device__ float  g_m2[GG * 256];
__device__ __nv_bfloat16 g_wthi[128 * 128];   // W^T split-high (n-major [n][k])
__device__ __nv_bfloat16 g_wtlo[128 * 128];   // W^T split-low

// ---------------- CSR build ----------------
__global__ void hist_kernel(const int* __restrict__ edst) {
    int e = blockIdx.x * blockDim.x + threadIdx.x;
    if (e < EE) atomicAdd(&g_rowptr[edst[e] + 1], 1);
}

// inclusive scan, single block of 1024, chunked (2 passes over data)
__global__ void scan_kernel(int* a, int n) {
    __shared__ int s[1024];
    int tid = threadIdx.x;
    int chunk = (n + 1023) >> 10;
    int beg = tid * chunk;
    int end = beg + chunk; if (end > n) end = n;
    int sum = 0;
    for (int i = beg; i < end; ++i) sum += a[i];
    s[tid] = sum;
    __syncthreads();
    for (int off = 1; off < 1024; off <<= 1) {
        int t = (tid >= off) ? s[tid - off] : 0;
        __syncthreads();
        s[tid] += t;
        __syncthreads();
    }
    int run = (tid > 0) ? s[tid - 1] : 0;
    for (int i = beg; i < end; ++i) { run += a[i]; a[i] = run; }
}

__global__ void fill_kernel(const int* __restrict__ esrc, const int* __restrict__ edst) {
    int e = blockIdx.x * blockDim.x + threadIdx.x;
    if (e >= EE) return;
    int d = edst[e];
    int pos = atomicAdd(&g_cursor[d], 1);
    g_col[g_rowptr[d] + pos] = esrc[e];
}

// ---------------- layer 0 aggregation: t = 2*h + sum_in(h), 78 dims ----------------
__global__ void agg0_kernel(const float* __restrict__ H) {
    int w = (blockIdx.x * blockDim.x + threadIdx.x) >> 5;
    if (w >= NN) return;
    int lid = threadIdx.x & 31;
    const float* hr = H + (size_t)w * 78;
    float a0 = 2.f * hr[lid];
    float a1 = 2.f * hr[lid + 32];
    float a2 = (lid < 14) ? 2.f * hr[lid + 64] : 0.f;
    int beg = g_rowptr[w], end = g_rowptr[w + 1];
    int j = beg;
    for (; j + 2 <= end; j += 2) {
        int s0 = g_col[j], s1 = g_col[j + 1];
        const float* h0 = H + (size_t)s0 * 78;
        const float* h1 = H + (size_t)s1 * 78;
        float x0 = h0[lid], y0 = h0[lid + 32];
        float x1 = h1[lid], y1 = h1[lid + 32];
        float z0 = (lid < 14) ? h0[lid + 64] : 0.f;
        float z1 = (lid < 14) ? h1[lid + 64] : 0.f;
        a0 += x0 + x1; a1 += y0 + y1; a2 += z0 + z1;
    }
    if (j < end) {
        const float* hs = H + (size_t)g_col[j] * 78;
        a0 += hs[lid];
        a1 += hs[lid + 32];
        if (lid < 14) a2 += hs[lid + 64];
    }
    float* t = g_bufA + (size_t)w * 128;
    t[lid] = a0;
    t[lid + 32] = a1;
    t[lid + 64] = (lid < 14) ? a2 : 0.f;
    t[lid + 96] = 0.f;   // zero-pad K 78..127 so GEMM padding is clean
}

// ---------------- elementwise: X = relu(bn(Y)) fp16, BN finalize folded in ----------------
__global__ void bnrelu_kernel(const __half* __restrict__ Yin, __half* __restrict__ Xout,
                              const float* __restrict__ stats, const float* __restrict__ gamma,
                              const float* __restrict__ beta) {
    __shared__ float ssc[128], ssh[128];
    int tid = threadIdx.x;
    if (tid < 128) {
        const float invn = 1.f / NN;
        float mu = stats[tid] * invn;
        float var = stats[128 + tid] * invn - mu * mu;
        float s = gamma[tid] * rsqrtf(var + 1e-5f);
        ssc[tid] = s;
        ssh[tid] = beta[tid] - mu * s;
    }
    __syncthreads();
    const __half2* Y2 = (const __half2*)Yin;
    __half2* X2 = (__half2*)Xout;
    int total = NN * 64;
    for (int i = blockIdx.x * blockDim.x + tid; i < total; i += gridDim.x * blockDim.x) {
        int c0 = (i & 63) * 2;
        float2 f = __half22float2(Y2[i]);
        float v0 = fmaxf(0.f, f.x * ssc[c0] + ssh[c0]);
        float v1 = fmaxf(0.f, f.y * ssc[c0 + 1] + ssh[c0 + 1]);
        X2[i] = __floats2half2_rn(v0, v1);
    }
}

// ---------------- mid-layer aggregation: t = 2*x[n] + sum_{src} x[src] (fp16 X) ----------
// pairwise HADD2 then fp32 accumulate (1 fp16 rounding per neighbor pair)
__global__ void agg_kernel(const __half* __restrict__ Xin, float* __restrict__ Tout) {
    int w = (blockIdx.x * blockDim.x + threadIdx.x) >> 5;
    if (w >= NN) return;
    int lid = threadIdx.x & 31;
    const uint2* X2 = (const uint2*)Xin;   // 4 halves per uint2, 32 per row

    uint2 self = X2[(size_t)w * 32 + lid];
    float2 f0 = __half22float2(*(__half2*)&self.x);
    float2 f1 = __half22float2(*(__half2*)&self.y);
    float a0 = 2.f * f0.x, a1 = 2.f * f0.y, a2 = 2.f * f1.x, a3 = 2.f * f1.y;

    int beg = g_rowptr[w], end = g_rowptr[w + 1];
    int j = beg;
    for (; j + 2 <= end; j += 2) {
        int s0 = g_col[j], s1 = g_col[j + 1];
        uint2 r0 = X2[(size_t)s0 * 32 + lid];
        uint2 r1 = X2[(size_t)s1 * 32 + lid];
        __half2 h0 = __hadd2(*(__half2*)&r0.x, *(__half2*)&r1.x);
        __half2 h1 = __hadd2(*(__half2*)&r0.y, *(__half2*)&r1.y);
        float2 u0 = __half22float2(h0);
        float2 u1 = __half22float2(h1);
        a0 += u0.x; a1 += u0.y; a2 += u1.x; a3 += u1.y;
    }
    if (j < end) {
        uint2 r0 = X2[(size_t)g_col[j] * 32 + lid];
        float2 u0 = __half22float2(*(__half2*)&r0.x);
        float2 u1 = __half22float2(*(__half2*)&r0.y);
        a0 += u0.x; a1 += u0.y; a2 += u1.x; a3 += u1.y;
    }
    ((float4*)Tout)[(size_t)w * 32 + lid] = make_float4(a0, a1, a2, a3);
}

// ---------------- readout: xg[graph] += x[n] (X already post-BN/ReLU) ----------------
__global__ void readout_kernel(const __half* __restrict__ Xin, const int* __restrict__ gid) {
    int w = (blockIdx.x * blockDim.x + threadIdx.x) >> 5;
    if (w >= NN) return;
    int lid = threadIdx.x & 31;
    uint2 raw = ((const uint2*)Xin)[(size_t)w * 32 + lid];
    float2 f0 = __half22float2(*(__half2*)&raw.x);
    float2 f1 = __half22float2(*(__half2*)&raw.y);
    int g = gid[w];
    float* dst = &g_xg[(size_t)g * 128 + lid * 4];
    atomicAdd(dst + 0, f0.x);
    atomicAdd(dst + 1, f0.y);
    atomicAdd(dst + 2, f1.x);
    atomicAdd(dst + 3, f1.y);
}

// ---------------- weight transpose + bf16 split (once per layer, tiny) ----------------
__global__ void wsplit_kernel(const float* __restrict__ W, int K,
                              __nv_bfloat16* __restrict__ Hi, __nv_bfloat16* __restrict__ Lo) {
    int i = blockIdx.x * blockDim.x + threadIdx.x;
    if (i >= 128 * 128) return;
    int k = i >> 7, n = i & 127;
    float w = (k < K) ? W[k * 128 + n] : 0.f;   // zero-pad K
    __nv_bfloat16 h = __float2bfloat16(w);
    Hi[n * 128 + k] = h;
    Lo[n * 128 + k] = __float2bfloat16(w - __bfloat162float(h));
}

// ---------------- HMMA helpers ----------------
__device__ __forceinline__ void mma16816(float c[4], uint32_t a0, uint32_t a1,
                                         uint32_t a2, uint32_t a3,
                                         uint32_t b0, uint32_t b1) {
    asm volatile(
        "mma.sync.aligned.m16n8k16.row.col.f32.bf16.bf16.f32 "
        "{%0,%1,%2,%3}, {%4,%5,%6,%7}, {%8,%9}, {%0,%1,%2,%3};"
        : "+f"(c[0]), "+f"(c[1]), "+f"(c[2]), "+f"(c[3])
        : "r"(a0), "r"(a1), "r"(a2), "r"(a3), "r"(b0), "r"(b1));
}

__device__ __forceinline__ uint32_t pack_bf16(float x, float y) {
    __nv_bfloat162 p;
    p.x = __float2bfloat16(x);
    p.y = __float2bfloat16(y);
    return *(uint32_t*)&p;
}

// ---------------- tensor GEMM: y[rows,128] = T[rows,128] @ W[128,128] + bscale*b --------
// 128x128 CTA tile, 8 warps as 4(m)x2(n): warp = 32 rows x 64 cols (halves B smem traffic).
// mma.sync m16n8k16 bf16, 3-term split. Fused bias + BN stats; y stored fp16.
#define PITCH 72
__global__ void __launch_bounds__(256, 2) gemm_mma_kernel(
    const float* __restrict__ T, const __nv_bfloat16* __restrict__ WtHi,
    const __nv_bfloat16* __restrict__ WtLo, const float* __restrict__ bias,
    float bscale, int rows, __half* __restrict__ Y, float* __restrict__ stats) {
    extern __shared__ char smem[];
    __nv_bfloat16* Ah = (__nv_bfloat16*)smem;           // [128][72]
    __nv_bfloat16* Al = Ah + 128 * PITCH;
    __nv_bfloat16* Bh = Al + 128 * PITCH;
    __nv_bfloat16* Bl = Bh + 128 * PITCH;
    float* sbias = (float*)(Bl + 128 * PITCH);          // 128
    float* sstat = sbias + 128;                         // 256 (sum|sq)

    int tid = threadIdx.x;
    int lane = tid & 31, wid = tid >> 5;
    int q = lane & 3, rsel = lane >> 2;
    int mw = wid & 3, nw = wid >> 2;
    int m0 = mw * 32, n0 = nw * 64;
    int row0 = blockIdx.x * 128;

    if (tid < 128) sbias[tid] = bscale * bias[tid];
    sstat[tid] = 0.f;

    float acc[2][8][4];
#pragma unroll
    for (int i = 0; i < 2; ++i)
#pragma unroll
        for (int j = 0; j < 8; ++j)
#pragma unroll
            for (int p = 0; p < 4; ++p) acc[i][j][p] = 0.f;

    for (int kc = 0; kc < 128; kc += 64) {
        // load + split A chunk [128 rows][64 k] fp32 -> bf16 hi/lo
        for (int idx = tid; idx < 2048; idx += 256) {
            int r = idx >> 4, c4 = idx & 15;
            int gr = row0 + r;
            float4 v = make_float4(0.f, 0.f, 0.f, 0.f);
            if (gr < rows) v = *(const float4*)&T[(size_t)gr * 128 + kc + c4 * 4];
            uint32_t h01 = pack_bf16(v.x, v.y), h23 = pack_bf16(v.z, v.w);
            __nv_bfloat162 hp0 = *(__nv_bfloat162*)&h01;
            __nv_bfloat162 hp1 = *(__nv_bfloat162*)&h23;
            uint32_t l01 = pack_bf16(v.x - __bfloat162float(hp0.x),
                                     v.y - __bfloat162float(hp0.y));
            uint32_t l23 = pack_bf16(v.z - __bfloat162float(hp1.x),
                                     v.w - __bfloat162float(hp1.y));
            uint2 hh = make_uint2(h01, h23), ll = make_uint2(l01, l23);
            *(uint2*)&Ah[r * PITCH + c4 * 4] = hh;
            *(uint2*)&Al[r * PITCH + c4 * 4] = ll;
        }
        // load B chunk [128 n][64 k] pre-split bf16
        for (int idx = tid; idx < 1024; idx += 256) {
            int r = idx >> 3, c8 = idx & 7;
            *(uint4*)&Bh[r * PITCH + c8 * 8] = *(const uint4*)&WtHi[r * 128 + kc + c8 * 8];
            *(uint4*)&Bl[r * PITCH + c8 * 8] = *(const uint4*)&WtLo[r * 128 + kc + c8 * 8];
        }
        __syncthreads();

#pragma unroll
        for (int term = 0; term < 3; ++term) {
            const __nv_bfloat16* Ab = (term == 1) ? Al : Ah;
            const __nv_bfloat16* Bb = (term == 2) ? Bl : Bh;
#pragma unroll
            for (int ks = 0; ks < 64; ks += 16) {
                uint32_t a[2][4];
#pragma unroll
                for (int i = 0; i < 2; ++i) {
                    const __nv_bfloat16* ar = Ab + (m0 + i * 16 + rsel) * PITCH + ks + 2 * q;
                    a[i][0] = *(const uint32_t*)ar;
                    a[i][1] = *(const uint32_t*)(ar + 8 * PITCH);
                    a[i][2] = *(const uint32_t*)(ar + 8);
                    a[i][3] = *(const uint32_t*)(ar + 8 * PITCH + 8);
                }
#pragma unroll
                for (int j = 0; j < 8; ++j) {
                    const __nv_bfloat16* br = Bb + (n0 + j * 8 + rsel) * PITCH + ks + 2 * q;
                    uint32_t b0 = *(const uint32_t*)br;
                    uint32_t b1 = *(const uint32_t*)(br + 8);
                    mma16816(acc[0][j], a[0][0], a[0][1], a[0][2], a[0][3], b0, b1);
                    mma16816(acc[1][j], a[1][0], a[1][1], a[1][2], a[1][3], b0, b1);
                }
            }
        }
        __syncthreads();
    }

    // epilogue: bias, fp16 store, BN stats (from exact fp32 values)
#pragma unroll
    for (int i = 0; i < 2; ++i) {
        int r_lo = row0 + m0 + i * 16 + rsel, r_hi = r_lo + 8;
        bool vlo = r_lo < rows, vhi = r_hi < rows;
#pragma unroll
        for (int j = 0; j < 8; ++j) {
            int c0 = n0 + j * 8 + 2 * q;
            float b0 = sbias[c0], b1 = sbias[c0 + 1];
            float v00 = vlo ? acc[i][j][0] + b0 : 0.f;
            float v01 = vlo ? acc[i][j][1] + b1 : 0.f;
            float v10 = vhi ? acc[i][j][2] + b0 : 0.f;
            float v11 = vhi ? acc[i][j][3] + b1 : 0.f;
            if (vlo) *(__half2*)&Y[(size_t)r_lo * 128 + c0] = __floats2half2_rn(v00, v01);
            if (vhi) *(__half2*)&Y[(size_t)r_hi * 128 + c0] = __floats2half2_rn(v10, v11);
            float s0 = v00 + v10, s1 = v01 + v11;
            float q0 = v00 * v00 + v10 * v10, q1 = v01 * v01 + v11 * v11;
#pragma unroll
            for (int off = 4; off <= 16; off <<= 1) {
                s0 += __shfl_xor_sync(0xFFFFFFFFu, s0, off);
                s1 += __shfl_xor_sync(0xFFFFFFFFu, s1, off);
                q0 += __shfl_xor_sync(0xFFFFFFFFu, q0, off);
                q1 += __shfl_xor_sync(0xFFFFFFFFu, q1, off);
            }
            if (rsel == 0) {
                atomicAdd(&sstat[c0], s0);
                atomicAdd(&sstat[c0 + 1], s1);
                atomicAdd(&sstat[128 + c0], q0);
                atomicAdd(&sstat[128 + c0 + 1], q1);
            }
        }
    }
    __syncthreads();
    atomicAdd(&stats[tid], sstat[tid]);
}

// ---------------- small MLP GEMM (thread-per-output) ----------------
__global__ void gemm_small_kernel(const float* __restrict__ X, const float* __restrict__ W,
                                  const float* __restrict__ bias, int R, int K, int C,
                                  float* __restrict__ Y, float* __restrict__ stats) {
    int c = blockIdx.x * 32 + (threadIdx.x & 31);
    int r = blockIdx.y * 8 + (threadIdx.x >> 5);
    if (c >= C || r >= R) return;
    float acc = bias[c];
    const float* xr = X + (size_t)r * K;
    for (int k = 0; k < K; ++k) acc = fmaf(xr[k], W[(size_t)k * C + c], acc);
    Y[(size_t)r * C + c] = acc;
    atomicAdd(&stats[c], acc);
    atomicAdd(&stats[C + c], acc * acc);
}

// norm+relu with BN finalize folded in (stats -> scale/shift per element)
__global__ void norm_relu_kernel(float* __restrict__ Y, const float* __restrict__ stats,
                                 const float* __restrict__ gamma, const float* __restrict__ beta,
                                 float invn, int total, int C) {
    int i = blockIdx.x * blockDim.x + threadIdx.x;
    if (i >= total) return;
    int c = i % C;
    float mu = stats[c] * invn;
    float var = stats[C + c] * invn - mu * mu;
    float s = gamma[c] * rsqrtf(var + 1e-5f);
    float v = (Y[i] - mu) * s + beta[c];
    Y[i] = fmaxf(v, 0.f);
}

__global__ void fc2_kernel(const float* __restrict__ X, const float* __restrict__ W,
                           const float* __restrict__ bias, float* __restrict__ out) {
    int c = blockIdx.x * 32 + (threadIdx.x & 31);
    int g = blockIdx.y * 8 + (threadIdx.x >> 5);
    if (c >= NCOUT || g >= GG) return;
    float acc = bias[204 + c];
    const float* xr = X + (size_t)g * 256;
    for (int k = 0; k < 256; ++k) acc = fmaf(xr[k], W[(size_t)k * 408 + 204 + c], acc);
    out[(size_t)g * NCOUT + c] = 1.f / (1.f + expf(-acc));
}

// ---------------- host orchestration ----------------
extern "C" void kernel_launch(void* const* d_in, const int* in_sizes, int n_in,
                              void* d_out, int out_size) {
    const float* h        = (const float*)d_in[0];
    const int*   esrc     = (const int*)d_in[1];
    const int*   edst     = (const int*)d_in[2];
    const int*   gid      = (const int*)d_in[3];
    const float* W1       = (const float*)d_in[4];
    const float* b1       = (const float*)d_in[5];
    const float* g1_gamma = (const float*)d_in[6];
    const float* g1_beta  = (const float*)d_in[7];
    const float* Wg       = (const float*)d_in[8];
    const float* bg       = (const float*)d_in[9];
    const float* gg       = (const float*)d_in[10];
    const float* gb       = (const float*)d_in[11];
    const float* fc1_W    = (const float*)d_in[12];
    const float* fc1_b    = (const float*)d_in[13];
    const float* bn1_g    = (const float*)d_in[14];
    const float* bn1_b    = (const float*)d_in[15];
    const float* lin_W    = (const float*)d_in[16];
    const float* lin_b    = (const float*)d_in[17];
    const float* lbn_g    = (const float*)d_in[18];
    const float* lbn_b    = (const float*)d_in[19];
    const float* fc2_W    = (const float*)d_in[20];
    const float* fc2_b    = (const float*)d_in[21];
    float* out = (float*)d_out;

    float *bufA, *stats, *xg, *m1, *m2;
    __half *bufY, *bufX;
    int *rowptr, *cursor;
    __nv_bfloat16 *wthi, *wtlo;
    cudaGetSymbolAddress((void**)&bufA, g_bufA);
    cudaGetSymbolAddress((void**)&bufY, g_bufY);
    cudaGetSymbolAddress((void**)&bufX, g_bufX);
    cudaGetSymbolAddress((void**)&stats, g_stats);
    cudaGetSymbolAddress((void**)&xg, g_xg);
    cudaGetSymbolAddress((void**)&m1, g_m1);
    cudaGetSymbolAddress((void**)&m2, g_m2);
    cudaGetSymbolAddress((void**)&rowptr, g_rowptr);
    cudaGetSymbolAddress((void**)&cursor, g_cursor);
    cudaGetSymbolAddress((void**)&wthi, g_wthi);
    cudaGetSymbolAddress((void**)&wtlo, g_wtlo);

    const int SMEMMA = 4 * 128 * PITCH * 2 + 128 * 4 + 256 * 4;   // 75264
    cudaFuncSetAttribute(gemm_mma_kernel, cudaFuncAttributeMaxDynamicSharedMemorySize, SMEMMA);

    const int WB = (NN * 32 + 255) / 256;   // warp-per-node grids
    const int EB = (EE + 255) / 256;
    const int GBt = (NN + 127) / 128;       // 782 GEMM tiles
    const int BNB = 6250;                   // bnrelu grid (grid-stride x4)

    // ---- CSR build (once per launch; reused for all 5 layers) ----
    cudaMemsetAsync(rowptr, 0, (NN + 1) * sizeof(int));
    hist_kernel<<<EB, 256>>>(edst);
    scan_kernel<<<1, 1024>>>(rowptr, NN + 1);
    cudaMemsetAsync(cursor, 0, NN * sizeof(int));
    fill_kernel<<<EB, 256>>>(esrc, edst);

    // single upfront zero for all stats buffers + xg
    cudaMemsetAsync(stats, 0, 8 * 1024 * sizeof(float));
    cudaMemsetAsync(xg, 0, GG * 128 * sizeof(float));

    // ---- layer 0 ----
    agg0_kernel<<<WB, 256>>>(h);
    wsplit_kernel<<<64, 256>>>(W1, 78, wthi, wtlo);
    gemm_mma_kernel<<<GBt, 256, SMEMMA>>>(bufA, wthi, wtlo, b1, 2.f, NN, bufY, stats);

    // ---- layers 1..4 (BN+ReLU as separate elementwise pass) ----
    const float* gmas[5] = {g1_gamma, gg, gg + 128, gg + 256, gg + 384};
    const float* btas[5] = {g1_beta,  gb, gb + 128, gb + 256, gb + 384};
    for (int l = 0; l < 4; ++l) {
        float* stPrev = stats + l * 1024;
        float* st = stats + (l + 1) * 1024;
        bnrelu_kernel<<<BNB, 256>>>(bufY, bufX, stPrev, gmas[l], btas[l]);
        agg_kernel<<<WB, 256>>>(bufX, bufA);
        wsplit_kernel<<<64, 256>>>(Wg + (size_t)l * 128 * 128, 128, wthi, wtlo);
        gemm_mma_kernel<<<GBt, 256, SMEMMA>>>(bufA, wthi, wtlo, bg + l * 128, 2.f, NN, bufY, st);
    }

    // ---- final BN+ReLU + graph sum readout ----
    bnrelu_kernel<<<BNB, 256>>>(bufY, bufX, stats + 4 * 1024, gmas[4], btas[4]);
    readout_kernel<<<WB, 256>>>(bufX, gid);

    // ---- MLP head ----
    float* st5 = stats + 5 * 1024;
    float* st6 = stats + 6 * 1024;
    gemm_small_kernel<<<dim3(512 / 32, GG / 8), 256>>>(xg, fc1_W, fc1_b, GG, 128, 512, m1, st5);
    norm_relu_kernel<<<(GG * 512 + 255) / 256, 256>>>(m1, st5, bn1_g, bn1_b, 1.f / GG,
                                                      GG * 512, 512);

    gemm_small_kernel<<<dim3(256 / 32, GG / 8), 256>>>(m1, lin_W, lin_b, GG, 512, 256, m2, st6);
    norm_relu_kernel<<<(GG * 256 + 255) / 256, 256>>>(m2, st6, lbn_g, lbn_b, 1.f / GG,
                                                      GG * 256, 256);

    fc2_kernel<<<dim3(7, GG / 8), 256>>>(m2, fc2_W, fc2_b, out);
}

// round 7
// speedup vs baseline: 2.0983x; 1.1785x over previous
#include <cuda_runtime.h>
#include <cuda_fp16.h>
#include <math.h>
#include <stdint.h>

#define NN 100000
#define EE 1600000
#define GG 2048
#define NCOUT 204

// ---------------- static scratch (no runtime allocation allowed) ----------------
__device__ __half g_bufT[NN * 128];      // t (GEMM input, fp16)
__device__ __half g_bufY[NN * 128];      // y (pre-BN GEMM output, fp16)
__device__ __half g_bufX[NN * 128];      // x = relu(bn(y)) (fp16)
__device__ int    g_rowptr[NN + 1];
__device__ int    g_cursor[NN];
__device__ int    g_col[EE];
__device__ float  g_stats[8 * 1024];     // per-layer [sum(0..C) | sumsq(C..2C)]
__device__ float  g_xg[GG * 128];
__device__ float  g_m1[GG * 512];
__device__ float  g_m2[GG * 256];
__device__ __half g_wt[128 * 128];       // W^T fp16 (n-major [n][k])

// ---------------- W convert (+ first-call scratch zeroing; replaces memsets) ----------
__global__ void wcvt_kernel(const float* __restrict__ W, int K, __half* __restrict__ Wt,
                            int init) {
    int i = blockIdx.x * blockDim.x + threadIdx.x;   // 16384 threads
    if (init) {
        for (int j = i; j < NN + 1; j += 16384) g_rowptr[j] = 0;
        for (int j = i; j < 8 * 1024; j += 16384) g_stats[j] = 0.f;
    }
    if (i < 128 * 128) {
        int k = i >> 7, n = i & 127;
        float w = (k < K) ? W[k * 128 + n] : 0.f;   // zero-pad K
        Wt[n * 128 + k] = __float2half(w);
    }
}

// ---------------- CSR build ----------------
__global__ void hist_kernel(const int* __restrict__ edst) {
    int e = blockIdx.x * blockDim.x + threadIdx.x;
    if (e < NN) g_cursor[e] = 0;                    // fold cursor zeroing in
    if (e < EE) atomicAdd(&g_rowptr[edst[e] + 1], 1);
}

// inclusive scan, single block of 1024, chunked (2 passes over data)
__global__ void scan_kernel(int* a, int n) {
    __shared__ int s[1024];
    int tid = threadIdx.x;
    int chunk = (n + 1023) >> 10;
    int beg = tid * chunk;
    int end = beg + chunk; if (end > n) end = n;
    int sum = 0;
    for (int i = beg; i < end; ++i) sum += a[i];
    s[tid] = sum;
    __syncthreads();
    for (int off = 1; off < 1024; off <<= 1) {
        int t = (tid >= off) ? s[tid - off] : 0;
        __syncthreads();
        s[tid] += t;
        __syncthreads();
    }
    int run = (tid > 0) ? s[tid - 1] : 0;
    for (int i = beg; i < end; ++i) { run += a[i]; a[i] = run; }
}

__global__ void fill_kernel(const int* __restrict__ esrc, const int* __restrict__ edst) {
    int e = blockIdx.x * blockDim.x + threadIdx.x;
    if (e >= EE) return;
    int d = edst[e];
    int pos = atomicAdd(&g_cursor[d], 1);
    g_col[g_rowptr[d] + pos] = esrc[e];
}

// ---------------- layer 0 aggregation: t = 2*h + sum_in(h), 78 dims -> fp16 -------------
__global__ void agg0_kernel(const float* __restrict__ H) {
    int w = (blockIdx.x * blockDim.x + threadIdx.x) >> 5;
    if (w >= NN) return;
    int lid = threadIdx.x & 31;
    const float* hr = H + (size_t)w * 78;
    float a0 = 2.f * hr[lid];
    float a1 = 2.f * hr[lid + 32];
    float a2 = (lid < 14) ? 2.f * hr[lid + 64] : 0.f;
    int beg = g_rowptr[w], end = g_rowptr[w + 1];
    int j = beg;
    for (; j + 2 <= end; j += 2) {
        int s0 = g_col[j], s1 = g_col[j + 1];
        const float* h0 = H + (size_t)s0 * 78;
        const float* h1 = H + (size_t)s1 * 78;
        float x0 = h0[lid], y0 = h0[lid + 32];
        float x1 = h1[lid], y1 = h1[lid + 32];
        float z0 = (lid < 14) ? h0[lid + 64] : 0.f;
        float z1 = (lid < 14) ? h1[lid + 64] : 0.f;
        a0 += x0 + x1; a1 += y0 + y1; a2 += z0 + z1;
    }
    if (j < end) {
        const float* hs = H + (size_t)g_col[j] * 78;
        a0 += hs[lid];
        a1 += hs[lid + 32];
        if (lid < 14) a2 += hs[lid + 64];
    }
    __half* t = g_bufT + (size_t)w * 128;
    t[lid] = __float2half(a0);
    t[lid + 32] = __float2half(a1);
    t[lid + 64] = (lid < 14) ? __float2half(a2) : __float2half(0.f);
    t[lid + 96] = __float2half(0.f);   // zero-pad K 78..127
}

// ---------------- elementwise: X = relu(bn(Y)) fp16, BN finalize folded in ----------------
__global__ void bnrelu_kernel(const __half* __restrict__ Yin, __half* __restrict__ Xout,
                              const float* __restrict__ stats, const float* __restrict__ gamma,
                              const float* __restrict__ beta) {
    __shared__ float ssc[128], ssh[128];
    int tid = threadIdx.x;
    if (tid < 128) {
        const float invn = 1.f / NN;
        float mu = stats[tid] * invn;
        float var = stats[128 + tid] * invn - mu * mu;
        float s = gamma[tid] * rsqrtf(var + 1e-5f);
        ssc[tid] = s;
        ssh[tid] = beta[tid] - mu * s;
    }
    __syncthreads();
    const __half2* Y2 = (const __half2*)Yin;
    __half2* X2 = (__half2*)Xout;
    int total = NN * 64;
    for (int i = blockIdx.x * blockDim.x + tid; i < total; i += gridDim.x * blockDim.x) {
        int c0 = (i & 63) * 2;
        float2 f = __half22float2(Y2[i]);
        float v0 = fmaxf(0.f, f.x * ssc[c0] + ssh[c0]);
        float v1 = fmaxf(0.f, f.y * ssc[c0 + 1] + ssh[c0 + 1]);
        X2[i] = __floats2half2_rn(v0, v1);
    }
}

// ---------------- mid-layer aggregation: t = 2*x[n] + sum_{src} x[src] -> fp16 -----------
// unroll-4 with batched loads for MLP; pairwise HADD2 then fp32 accumulate
__global__ void agg_kernel(const __half* __restrict__ Xin, __half* __restrict__ Tout) {
    int w = (blockIdx.x * blockDim.x + threadIdx.x) >> 5;
    if (w >= NN) return;
    int lid = threadIdx.x & 31;
    const uint2* X2 = (const uint2*)Xin;   // 4 halves per uint2, 32 per row

    uint2 self = X2[(size_t)w * 32 + lid];
    float2 f0 = __half22float2(*(__half2*)&self.x);
    float2 f1 = __half22float2(*(__half2*)&self.y);
    float a0 = 2.f * f0.x, a1 = 2.f * f0.y, a2 = 2.f * f1.x, a3 = 2.f * f1.y;

    int beg = g_rowptr[w], end = g_rowptr[w + 1];
    int j = beg;
    for (; j + 4 <= end; j += 4) {
        int s0 = g_col[j], s1 = g_col[j + 1], s2 = g_col[j + 2], s3 = g_col[j + 3];
        uint2 r0 = X2[(size_t)s0 * 32 + lid];
        uint2 r1 = X2[(size_t)s1 * 32 + lid];
        uint2 r2 = X2[(size_t)s2 * 32 + lid];
        uint2 r3 = X2[(size_t)s3 * 32 + lid];
        __half2 p0 = __hadd2(*(__half2*)&r0.x, *(__half2*)&r1.x);
        __half2 p1 = __hadd2(*(__half2*)&r0.y, *(__half2*)&r1.y);
        __half2 q0 = __hadd2(*(__half2*)&r2.x, *(__half2*)&r3.x);
        __half2 q1 = __hadd2(*(__half2*)&r2.y, *(__half2*)&r3.y);
        float2 u0 = __half22float2(p0), u1 = __half22float2(p1);
        float2 v0 = __half22float2(q0), v1 = __half22float2(q1);
        a0 += u0.x + v0.x; a1 += u0.y + v0.y;
        a2 += u1.x + v1.x; a3 += u1.y + v1.y;
    }
    for (; j < end; ++j) {
        uint2 r0 = X2[(size_t)g_col[j] * 32 + lid];
        float2 u0 = __half22float2(*(__half2*)&r0.x);
        float2 u1 = __half22float2(*(__half2*)&r0.y);
        a0 += u0.x; a1 += u0.y; a2 += u1.x; a3 += u1.y;
    }
    uint2 o;
    *(__half2*)&o.x = __floats2half2_rn(a0, a1);
    *(__half2*)&o.y = __floats2half2_rn(a2, a3);
    ((uint2*)Tout)[(size_t)w * 32 + lid] = o;
}

// ---------------- readout: xg[g] = sum of X rows in [lb(g), lb(g+1)) (gid sorted) --------
__global__ void readout_kernel(const __half* __restrict__ Xin, const int* __restrict__ gid,
                               float* __restrict__ xg) {
    int g = blockIdx.x;          // 2048 blocks
    int tid = threadIdx.x;       // 128 threads = one column each
    int lo = 0, hi = NN;
    while (lo < hi) { int mid = (lo + hi) >> 1; if (gid[mid] < g) lo = mid + 1; else hi = mid; }
    int beg = lo;
    hi = NN;
    while (lo < hi) { int mid = (lo + hi) >> 1; if (gid[mid] < g + 1) lo = mid + 1; else hi = mid; }
    int end = lo;
    float acc = 0.f;
    for (int r = beg; r < end; ++r)
        acc += __half2float(Xin[(size_t)r * 128 + tid]);
    xg[(size_t)g * 128 + tid] = acc;
}

// ---------------- HMMA fp16 helper ----------------
__device__ __forceinline__ void mma16816(float c[4], uint32_t a0, uint32_t a1,
                                         uint32_t a2, uint32_t a3,
                                         uint32_t b0, uint32_t b1) {
    asm volatile(
        "mma.sync.aligned.m16n8k16.row.col.f32.f16.f16.f32 "
        "{%0,%1,%2,%3}, {%4,%5,%6,%7}, {%8,%9}, {%0,%1,%2,%3};"
        : "+f"(c[0]), "+f"(c[1]), "+f"(c[2]), "+f"(c[3])
        : "r"(a0), "r"(a1), "r"(a2), "r"(a3), "r"(b0), "r"(b1));
}

// ---------------- tensor GEMM: y[rows,128] = T[rows,128] @ W[128,128] + bscale*b --------
// fp16 single-term. 128x128 CTA tile, 8 warps as 4(m)x2(n). K in 2 chunks of 64.
// Fused bias + BN stats; y stored fp16 (stats from exact fp32 accumulators).
#define PITCH 72
__global__ void __launch_bounds__(256, 2) gemm_mma_kernel(
    const __half* __restrict__ T, const __half* __restrict__ Wt,
    const float* __restrict__ bias, float bscale, int rows,
    __half* __restrict__ Y, float* __restrict__ stats) {
    extern __shared__ char smem[];
    __half* Ah = (__half*)smem;                 // [128][72]
    __half* Bh = Ah + 128 * PITCH;              // [128][72]
    float* sbias = (float*)(Bh + 128 * PITCH);  // 128
    float* sstat = sbias + 128;                 // 256 (sum|sq)

    int tid = threadIdx.x;
    int lane = tid & 31, wid = tid >> 5;
    int q = lane & 3, rsel = lane >> 2;
    int mw = wid & 3, nw = wid >> 2;
    int m0 = mw * 32, n0 = nw * 64;
    int row0 = blockIdx.x * 128;

    if (tid < 128) sbias[tid] = bscale * bias[tid];
    sstat[tid] = 0.f;

    float acc[2][8][4];
#pragma unroll
    for (int i = 0; i < 2; ++i)
#pragma unroll
        for (int j = 0; j < 8; ++j)
#pragma unroll
            for (int p = 0; p < 4; ++p) acc[i][j][p] = 0.f;

    for (int kc = 0; kc < 128; kc += 64) {
        // copy A chunk [128 rows][64 k] fp16 (8 uint4 per row)
        for (int idx = tid; idx < 1024; idx += 256) {
            int r = idx >> 3, c8 = idx & 7;
            int gr = row0 + r;
            uint4 v = make_uint4(0u, 0u, 0u, 0u);
            if (gr < rows) v = *(const uint4*)&T[(size_t)gr * 128 + kc + c8 * 8];
            *(uint4*)&Ah[r * PITCH + c8 * 8] = v;
        }
        // copy B chunk [128 n][64 k] fp16
        for (int idx = tid; idx < 1024; idx += 256) {
            int r = idx >> 3, c8 = idx & 7;
            *(uint4*)&Bh[r * PITCH + c8 * 8] = *(const uint4*)&Wt[r * 128 + kc + c8 * 8];
        }
        __syncthreads();

#pragma unroll
        for (int ks = 0; ks < 64; ks += 16) {
            uint32_t a[2][4];
#pragma unroll
            for (int i = 0; i < 2; ++i) {
                const __half* ar = Ah + (m0 + i * 16 + rsel) * PITCH + ks + 2 * q;
                a[i][0] = *(const uint32_t*)ar;
                a[i][1] = *(const uint32_t*)(ar + 8 * PITCH);
                a[i][2] = *(const uint32_t*)(ar + 8);
                a[i][3] = *(const uint32_t*)(ar + 8 * PITCH + 8);
            }
#pragma unroll
            for (int j = 0; j < 8; ++j) {
                const __half* br = Bh + (n0 + j * 8 + rsel) * PITCH + ks + 2 * q;
                uint32_t b0 = *(const uint32_t*)br;
                uint32_t b1 = *(const uint32_t*)(br + 8);
                mma16816(acc[0][j], a[0][0], a[0][1], a[0][2], a[0][3], b0, b1);
                mma16816(acc[1][j], a[1][0], a[1][1], a[1][2], a[1][3], b0, b1);
            }
        }
        __syncthreads();
    }

    // epilogue: bias, fp16 store, BN stats (from exact fp32 values)
#pragma unroll
    for (int i = 0; i < 2; ++i) {
        int r_lo = row0 + m0 + i * 16 + rsel, r_hi = r_lo + 8;
        bool vlo = r_lo < rows, vhi = r_hi < rows;
#pragma unroll
        for (int j = 0; j < 8; ++j) {
            int c0 = n0 + j * 8 + 2 * q;
            float b0 = sbias[c0], b1 = sbias[c0 + 1];
            float v00 = vlo ? acc[i][j][0] + b0 : 0.f;
            float v01 = vlo ? acc[i][j][1] + b1 : 0.f;
            float v10 = vhi ? acc[i][j][2] + b0 : 0.f;
            float v11 = vhi ? acc[i][j][3] + b1 : 0.f;
            if (vlo) *(__half2*)&Y[(size_t)r_lo * 128 + c0] = __floats2half2_rn(v00, v01);
            if (vhi) *(__half2*)&Y[(size_t)r_hi * 128 + c0] = __floats2half2_rn(v10, v11);
            float s0 = v00 + v10, s1 = v01 + v11;
            float q0 = v00 * v00 + v10 * v10, q1 = v01 * v01 + v11 * v11;
#pragma unroll
            for (int off = 4; off <= 16; off <<= 1) {
                s0 += __shfl_xor_sync(0xFFFFFFFFu, s0, off);
                s1 += __shfl_xor_sync(0xFFFFFFFFu, s1, off);
                q0 += __shfl_xor_sync(0xFFFFFFFFu, q0, off);
                q1 += __shfl_xor_sync(0xFFFFFFFFu, q1, off);
            }
            if (rsel == 0) {
                atomicAdd(&sstat[c0], s0);
                atomicAdd(&sstat[c0 + 1], s1);
                atomicAdd(&sstat[128 + c0], q0);
                atomicAdd(&sstat[128 + c0 + 1], q1);
            }
        }
    }
    __syncthreads();
    atomicAdd(&stats[tid], sstat[tid]);
}

// ---------------- small MLP GEMM (thread-per-output) ----------------
__global__ void gemm_small_kernel(const float* __restrict__ X, const float* __restrict__ W,
                                  const float* __restrict__ bias, int R, int K, int C,
                                  float* __restrict__ Y, float* __restrict__ stats) {
    int c = blockIdx.x * 32 + (threadIdx.x & 31);
    int r = blockIdx.y * 8 + (threadIdx.x >> 5);
    if (c >= C || r >= R) return;
    float acc = bias[c];
    const float* xr = X + (size_t)r * K;
    for (int k = 0; k < K; ++k) acc = fmaf(xr[k], W[(size_t)k * C + c], acc);
    Y[(size_t)r * C + c] = acc;
    atomicAdd(&stats[c], acc);
    atomicAdd(&stats[C + c], acc * acc);
}

// norm+relu with BN finalize folded in
__global__ void norm_relu_kernel(float* __restrict__ Y, const float* __restrict__ stats,
                                 const float* __restrict__ gamma, const float* __restrict__ beta,
                                 float invn, int total, int C) {
    int i = blockIdx.x * blockDim.x + threadIdx.x;
    if (i >= total) return;
    int c = i % C;
    float mu = stats[c] * invn;
    float var = stats[C + c] * invn - mu * mu;
    float s = gamma[c] * rsqrtf(var + 1e-5f);
    float v = (Y[i] - mu) * s + beta[c];
    Y[i] = fmaxf(v, 0.f);
}

__global__ void fc2_kernel(const float* __restrict__ X, const float* __restrict__ W,
                           const float* __restrict__ bias, float* __restrict__ out) {
    int c = blockIdx.x * 32 + (threadIdx.x & 31);
    int g = blockIdx.y * 8 + (threadIdx.x >> 5);
    if (c >= NCOUT || g >= GG) return;
    float acc = bias[204 + c];
    const float* xr = X + (size_t)g * 256;
    for (int k = 0; k < 256; ++k) acc = fmaf(xr[k], W[(size_t)k * 408 + 204 + c], acc);
    out[(size_t)g * NCOUT + c] = 1.f / (1.f + expf(-acc));
}

// ---------------- host orchestration ----------------
extern "C" void kernel_launch(void* const* d_in, const int* in_sizes, int n_in,
                              void* d_out, int out_size) {
    const float* h        = (const float*)d_in[0];
    const int*   esrc     = (const int*)d_in[1];
    const int*   edst     = (const int*)d_in[2];
    const int*   gid      = (const int*)d_in[3];
    const float* W1       = (const float*)d_in[4];
    const float* b1       = (const float*)d_in[5];
    const float* g1_gamma = (const float*)d_in[6];
    const float* g1_beta  = (const float*)d_in[7];
    const float* Wg       = (const float*)d_in[8];
    const float* bg       = (const float*)d_in[9];
    const float* gg       = (const float*)d_in[10];
    const float* gb       = (const float*)d_in[11];
    const float* fc1_W    = (const float*)d_in[12];
    const float* fc1_b    = (const float*)d_in[13];
    const float* bn1_g    = (const float*)d_in[14];
    const float* bn1_b    = (const float*)d_in[15];
    const float* lin_W    = (const float*)d_in[16];
    const float* lin_b    = (const float*)d_in[17];
    const float* lbn_g    = (const float*)d_in[18];
    const float* lbn_b    = (const float*)d_in[19];
    const float* fc2_W    = (const float*)d_in[20];
    const float* fc2_b    = (const float*)d_in[21];
    float* out = (float*)d_out;

    float *stats, *xg, *m1, *m2;
    __half *bufT, *bufY, *bufX, *wt;
    int *rowptr;
    cudaGetSymbolAddress((void**)&bufT, g_bufT);
    cudaGetSymbolAddress((void**)&bufY, g_bufY);
    cudaGetSymbolAddress((void**)&bufX, g_bufX);
    cudaGetSymbolAddress((void**)&stats, g_stats);
    cudaGetSymbolAddress((void**)&xg, g_xg);
    cudaGetSymbolAddress((void**)&m1, g_m1);
    cudaGetSymbolAddress((void**)&m2, g_m2);
    cudaGetSymbolAddress((void**)&rowptr, g_rowptr);
    cudaGetSymbolAddress((void**)&wt, g_wt);

    const int SMEMMA = 2 * 128 * PITCH * 2 + 128 * 4 + 256 * 4;   // 38400
    cudaFuncSetAttribute(gemm_mma_kernel, cudaFuncAttributeMaxDynamicSharedMemorySize, SMEMMA);

    const int WB = (NN * 32 + 255) / 256;   // warp-per-node grids
    const int EB = (EE + 255) / 256;
    const int GBt = (NN + 127) / 128;       // 782 GEMM tiles
    const int BNB = 6250;

    // ---- CSR build + layer 0 (no memsets: zeroing folded into wcvt/hist) ----
    wcvt_kernel<<<64, 256>>>(W1, 78, wt, 1);     // also zeroes rowptr + stats
    hist_kernel<<<EB, 256>>>(edst);              // also zeroes cursor
    scan_kernel<<<1, 1024>>>(rowptr, NN + 1);
    fill_kernel<<<EB, 256>>>(esrc, edst);
    agg0_kernel<<<WB, 256>>>(h);
    gemm_mma_kernel<<<GBt, 256, SMEMMA>>>(bufT, wt, b1, 2.f, NN, bufY, stats);

    // ---- layers 1..4 ----
    const float* gmas[5] = {g1_gamma, gg, gg + 128, gg + 256, gg + 384};
    const float* btas[5] = {g1_beta,  gb, gb + 128, gb + 256, gb + 384};
    for (int l = 0; l < 4; ++l) {
        float* stPrev = stats + l * 1024;
        float* st = stats + (l + 1) * 1024;
        bnrelu_kernel<<<BNB, 256>>>(bufY, bufX, stPrev, gmas[l], btas[l]);
        agg_kernel<<<WB, 256>>>(bufX, bufT);
        wcvt_kernel<<<64, 256>>>(Wg + (size_t)l * 128 * 128, 128, wt, 0);
        gemm_mma_kernel<<<GBt, 256, SMEMMA>>>(bufT, wt, bg + l * 128, 2.f, NN, bufY, st);
    }

    // ---- final BN+ReLU + sorted segment-sum readout (no atomics) ----
    bnrelu_kernel<<<BNB, 256>>>(bufY, bufX, stats + 4 * 1024, gmas[4], btas[4]);
    readout_kernel<<<GG, 128>>>(bufX, gid, xg);

    // ---- MLP head ----
    float* st5 = stats + 5 * 1024;
    float* st6 = stats + 6 * 1024;
    gemm_small_kernel<<<dim3(512 / 32, GG / 8), 256>>>(xg, fc1_W, fc1_b, GG, 128, 512, m1, st5);
    norm_relu_kernel<<<(GG * 512 + 255) / 256, 256>>>(m1, st5, bn1_g, bn1_b, 1.f / GG,
                                                      GG * 512, 512);

    gemm_small_kernel<<<dim3(256 / 32, GG / 8), 256>>>(m1, lin_W, lin_b, GG, 512, 256, m2, st6);
    norm_relu_kernel<<<(GG * 256 + 255) / 256, 256>>>(m2, st6, lbn_g, lbn_b, 1.f / GG,
                                                      GG * 256, 256);

    fc2_kernel<<<dim3(7, GG / 8), 256>>>(m2, fc2_W, fc2_b, out);
}

// round 8
// speedup vs baseline: 2.1762x; 1.0371x over previous
#include <cuda_runtime.h>
#include <cuda_fp16.h>
#include <math.h>
#include <stdint.h>

#define NN 100000
#define EE 1600000
#define GG 2048
#define NCOUT 204

// ---------------- static scratch (no runtime allocation allowed) ----------------
__device__ __half g_bufT[NN * 128];      // t (GEMM input, fp16)
__device__ __half g_bufY[NN * 128];      // y (pre-BN GEMM output, fp16)
__device__ __half g_bufX[NN * 128];      // x = relu(bn(y)) (fp16)
__device__ int    g_rowptr[NN + 1];
__device__ int    g_cursor[NN];
__device__ int    g_col[EE];
__device__ float  g_stats[8 * 1024];     // per-layer [sum(0..C) | sumsq(C..2C)]
__device__ float  g_xg[GG * 128];
__device__ float  g_m1[GG * 512];
__device__ float  g_m2[GG * 256];
__device__ __half g_wt[128 * 128];       // W^T fp16 (n-major [n][k])

// ---------------- W convert (+ first-call scratch zeroing; replaces memsets) ----------
__global__ void wcvt_kernel(const float* __restrict__ W, int K, __half* __restrict__ Wt,
                            int init) {
    int i = blockIdx.x * blockDim.x + threadIdx.x;   // 16384 threads
    if (init) {
        for (int j = i; j < NN + 1; j += 16384) g_rowptr[j] = 0;
        for (int j = i; j < 8 * 1024; j += 16384) g_stats[j] = 0.f;
    }
    if (i < 128 * 128) {
        int k = i >> 7, n = i & 127;
        float w = (k < K) ? W[k * 128 + n] : 0.f;   // zero-pad K
        Wt[n * 128 + k] = __float2half(w);
    }
}

// ---------------- CSR build ----------------
__global__ void hist_kernel(const int* __restrict__ edst) {
    int e = blockIdx.x * blockDim.x + threadIdx.x;
    if (e < NN) g_cursor[e] = 0;                    // fold cursor zeroing in
    if (e < EE) atomicAdd(&g_rowptr[edst[e] + 1], 1);
}

// inclusive scan, single block of 1024, chunked (2 passes over data)
__global__ void scan_kernel(int* a, int n) {
    __shared__ int s[1024];
    int tid = threadIdx.x;
    int chunk = (n + 1023) >> 10;
    int beg = tid * chunk;
    int end = beg + chunk; if (end > n) end = n;
    int sum = 0;
    for (int i = beg; i < end; ++i) sum += a[i];
    s[tid] = sum;
    __syncthreads();
    for (int off = 1; off < 1024; off <<= 1) {
        int t = (tid >= off) ? s[tid - off] : 0;
        __syncthreads();
        s[tid] += t;
        __syncthreads();
    }
    int run = (tid > 0) ? s[tid - 1] : 0;
    for (int i = beg; i < end; ++i) { run += a[i]; a[i] = run; }
}

__global__ void fill_kernel(const int* __restrict__ esrc, const int* __restrict__ edst) {
    int e = blockIdx.x * blockDim.x + threadIdx.x;
    if (e >= EE) return;
    int d = edst[e];
    int pos = atomicAdd(&g_cursor[d], 1);
    g_col[g_rowptr[d] + pos] = esrc[e];
}

// ---------------- layer 0 aggregation: t = 2*h + sum_in(h), 78 dims -> fp16 -------------
__global__ void agg0_kernel(const float* __restrict__ H) {
    int w = (blockIdx.x * blockDim.x + threadIdx.x) >> 5;
    if (w >= NN) return;
    int lid = threadIdx.x & 31;
    const float* hr = H + (size_t)w * 78;
    float a0 = 2.f * hr[lid];
    float a1 = 2.f * hr[lid + 32];
    float a2 = (lid < 14) ? 2.f * hr[lid + 64] : 0.f;
    int beg = g_rowptr[w], end = g_rowptr[w + 1];
    int j = beg;
    for (; j + 4 <= end; j += 4) {
        int s[4];
#pragma unroll
        for (int u = 0; u < 4; ++u) s[u] = g_col[j + u];
        float x[4], y[4], z[4];
#pragma unroll
        for (int u = 0; u < 4; ++u) {
            const float* hp = H + (size_t)s[u] * 78;
            x[u] = hp[lid];
            y[u] = hp[lid + 32];
            z[u] = (lid < 14) ? hp[lid + 64] : 0.f;
        }
        a0 += (x[0] + x[1]) + (x[2] + x[3]);
        a1 += (y[0] + y[1]) + (y[2] + y[3]);
        a2 += (z[0] + z[1]) + (z[2] + z[3]);
    }
    for (; j < end; ++j) {
        const float* hs = H + (size_t)g_col[j] * 78;
        a0 += hs[lid];
        a1 += hs[lid + 32];
        if (lid < 14) a2 += hs[lid + 64];
    }
    __half* t = g_bufT + (size_t)w * 128;
    t[lid] = __float2half(a0);
    t[lid + 32] = __float2half(a1);
    t[lid + 64] = (lid < 14) ? __float2half(a2) : __float2half(0.f);
    t[lid + 96] = __float2half(0.f);   // zero-pad K 78..127
}

// ---------------- elementwise: X = relu(bn(Y)) fp16, BN finalize folded in ----------------
__global__ void bnrelu_kernel(const __half* __restrict__ Yin, __half* __restrict__ Xout,
                              const float* __restrict__ stats, const float* __restrict__ gamma,
                              const float* __restrict__ beta) {
    __shared__ float ssc[128], ssh[128];
    int tid = threadIdx.x;
    if (tid < 128) {
        const float invn = 1.f / NN;
        float mu = stats[tid] * invn;
        float var = stats[128 + tid] * invn - mu * mu;
        float s = gamma[tid] * rsqrtf(var + 1e-5f);
        ssc[tid] = s;
        ssh[tid] = beta[tid] - mu * s;
    }
    __syncthreads();
    const __half2* Y2 = (const __half2*)Yin;
    __half2* X2 = (__half2*)Xout;
    int total = NN * 64;
    for (int i = blockIdx.x * blockDim.x + tid; i < total; i += gridDim.x * blockDim.x) {
        int c0 = (i & 63) * 2;
        float2 f = __half22float2(Y2[i]);
        float v0 = fmaxf(0.f, f.x * ssc[c0] + ssh[c0]);
        float v1 = fmaxf(0.f, f.y * ssc[c0 + 1] + ssh[c0 + 1]);
        X2[i] = __floats2half2_rn(v0, v1);
    }
}

// ---------------- mid-layer aggregation: t = 2*x[n] + sum_{src} x[src] -> fp16 -----------
// unroll-8 batched loads (MLP ~8); pairwise HADD2 then fp32 accumulate
__global__ void agg_kernel(const __half* __restrict__ Xin, __half* __restrict__ Tout) {
    int w = (blockIdx.x * blockDim.x + threadIdx.x) >> 5;
    if (w >= NN) return;
    int lid = threadIdx.x & 31;
    const uint2* X2 = (const uint2*)Xin;   // 4 halves per uint2, 32 per row

    uint2 self = X2[(size_t)w * 32 + lid];
    float2 f0 = __half22float2(*(__half2*)&self.x);
    float2 f1 = __half22float2(*(__half2*)&self.y);
    float a0 = 2.f * f0.x, a1 = 2.f * f0.y, a2 = 2.f * f1.x, a3 = 2.f * f1.y;

    int beg = g_rowptr[w], end = g_rowptr[w + 1];
    int j = beg;
    for (; j + 8 <= end; j += 8) {
        int s[8];
#pragma unroll
        for (int u = 0; u < 8; ++u) s[u] = g_col[j + u];
        uint2 r[8];
#pragma unroll
        for (int u = 0; u < 8; ++u) r[u] = X2[(size_t)s[u] * 32 + lid];
#pragma unroll
        for (int u = 0; u < 8; u += 2) {
            __half2 p0 = __hadd2(*(__half2*)&r[u].x, *(__half2*)&r[u + 1].x);
            __half2 p1 = __hadd2(*(__half2*)&r[u].y, *(__half2*)&r[u + 1].y);
            float2 u0 = __half22float2(p0), u1 = __half22float2(p1);
            a0 += u0.x; a1 += u0.y; a2 += u1.x; a3 += u1.y;
        }
    }
    for (; j < end; ++j) {
        uint2 r0 = X2[(size_t)g_col[j] * 32 + lid];
        float2 u0 = __half22float2(*(__half2*)&r0.x);
        float2 u1 = __half22float2(*(__half2*)&r0.y);
        a0 += u0.x; a1 += u0.y; a2 += u1.x; a3 += u1.y;
    }
    uint2 o;
    *(__half2*)&o.x = __floats2half2_rn(a0, a1);
    *(__half2*)&o.y = __floats2half2_rn(a2, a3);
    ((uint2*)Tout)[(size_t)w * 32 + lid] = o;
}

// ---------------- readout: xg[g] = sum relu(bn(y)) over rows of graph g (gid sorted) -----
// BN finalize + normalize fused in; no X materialization for the last layer.
__global__ void readout_kernel(const __half* __restrict__ Yin, const int* __restrict__ gid,
                               float* __restrict__ xg, const float* __restrict__ stats,
                               const float* __restrict__ gamma, const float* __restrict__ beta) {
    __shared__ float ssc[128], ssh[128];
    int tid = threadIdx.x;       // 128 threads = one column each
    {
        const float invn = 1.f / NN;
        float mu = stats[tid] * invn;
        float var = stats[128 + tid] * invn - mu * mu;
        float s = gamma[tid] * rsqrtf(var + 1e-5f);
        ssc[tid] = s;
        ssh[tid] = beta[tid] - mu * s;
    }
    __syncthreads();
    int g = blockIdx.x;          // 2048 blocks
    int lo = 0, hi = NN;
    while (lo < hi) { int mid = (lo + hi) >> 1; if (gid[mid] < g) lo = mid + 1; else hi = mid; }
    int beg = lo;
    hi = NN;
    while (lo < hi) { int mid = (lo + hi) >> 1; if (gid[mid] < g + 1) lo = mid + 1; else hi = mid; }
    int end = lo;
    float sc = ssc[tid], sh = ssh[tid];
    float acc = 0.f;
    for (int r = beg; r < end; ++r)
        acc += fmaxf(0.f, __half2float(Yin[(size_t)r * 128 + tid]) * sc + sh);
    xg[(size_t)g * 128 + tid] = acc;
}

// ---------------- HMMA fp16 helper ----------------
__device__ __forceinline__ void mma16816(float c[4], uint32_t a0, uint32_t a1,
                                         uint32_t a2, uint32_t a3,
                                         uint32_t b0, uint32_t b1) {
    asm volatile(
        "mma.sync.aligned.m16n8k16.row.col.f32.f16.f16.f32 "
        "{%0,%1,%2,%3}, {%4,%5,%6,%7}, {%8,%9}, {%0,%1,%2,%3};"
        : "+f"(c[0]), "+f"(c[1]), "+f"(c[2]), "+f"(c[3])
        : "r"(a0), "r"(a1), "r"(a2), "r"(a3), "r"(b0), "r"(b1));
}

// ---------------- tensor GEMM: y[rows,128] = T[rows,128] @ W[128,128] + bscale*b --------
// fp16 single-term, single K-stage (full tiles resident, one sync).
// 128x128 CTA tile, 8 warps as 4(m)x2(n). Fused bias + BN stats; y stored fp16.
#define PITCH 136
__global__ void __launch_bounds__(256, 2) gemm_mma_kernel(
    const __half* __restrict__ T, const __half* __restrict__ Wt,
    const float* __restrict__ bias, float bscale, int rows,
    __half* __restrict__ Y, float* __restrict__ stats) {
    extern __shared__ char smem[];
    __half* Ah = (__half*)smem;                 // [128][136]
    __half* Bh = Ah + 128 * PITCH;              // [128][136]
    float* sbias = (float*)(Bh + 128 * PITCH);  // 128
    float* sstat = sbias + 128;                 // 256 (sum|sq)

    int tid = threadIdx.x;
    int lane = tid & 31, wid = tid >> 5;
    int q = lane & 3, rsel = lane >> 2;
    int mw = wid & 3, nw = wid >> 2;
    int m0 = mw * 32, n0 = nw * 64;
    int row0 = blockIdx.x * 128;

    if (tid < 128) sbias[tid] = bscale * bias[tid];
    sstat[tid] = 0.f;

    // load full A tile [128][128] fp16 (16 uint4 per row) and B tile
    for (int idx = tid; idx < 2048; idx += 256) {
        int r = idx >> 4, c8 = idx & 15;
        int gr = row0 + r;
        uint4 v = make_uint4(0u, 0u, 0u, 0u);
        if (gr < rows) v = *(const uint4*)&T[(size_t)gr * 128 + c8 * 8];
        *(uint4*)&Ah[r * PITCH + c8 * 8] = v;
    }
    for (int idx = tid; idx < 2048; idx += 256) {
        int r = idx >> 4, c8 = idx & 15;
        *(uint4*)&Bh[r * PITCH + c8 * 8] = *(const uint4*)&Wt[r * 128 + c8 * 8];
    }
    __syncthreads();

    float acc[2][8][4];
#pragma unroll
    for (int i = 0; i < 2; ++i)
#pragma unroll
        for (int j = 0; j < 8; ++j)
#pragma unroll
            for (int p = 0; p < 4; ++p) acc[i][j][p] = 0.f;

#pragma unroll
    for (int ks = 0; ks < 128; ks += 16) {
        uint32_t a[2][4];
#pragma unroll
        for (int i = 0; i < 2; ++i) {
            const __half* ar = Ah + (m0 + i * 16 + rsel) * PITCH + ks + 2 * q;
            a[i][0] = *(const uint32_t*)ar;
            a[i][1] = *(const uint32_t*)(ar + 8 * PITCH);
            a[i][2] = *(const uint32_t*)(ar + 8);
            a[i][3] = *(const uint32_t*)(ar + 8 * PITCH + 8);
        }
#pragma unroll
        for (int j = 0; j < 8; ++j) {
            const __half* br = Bh + (n0 + j * 8 + rsel) * PITCH + ks + 2 * q;
            uint32_t b0 = *(const uint32_t*)br;
            uint32_t b1 = *(const uint32_t*)(br + 8);
            mma16816(acc[0][j], a[0][0], a[0][1], a[0][2], a[0][3], b0, b1);
            mma16816(acc[1][j], a[1][0], a[1][1], a[1][2], a[1][3], b0, b1);
        }
    }

    // epilogue: bias, fp16 store, BN stats (from exact fp32 values)
#pragma unroll
    for (int i = 0; i < 2; ++i) {
        int r_lo = row0 + m0 + i * 16 + rsel, r_hi = r_lo + 8;
        bool vlo = r_lo < rows, vhi = r_hi < rows;
#pragma unroll
        for (int j = 0; j < 8; ++j) {
            int c0 = n0 + j * 8 + 2 * q;
            float b0 = sbias[c0], b1 = sbias[c0 + 1];
            float v00 = vlo ? acc[i][j][0] + b0 : 0.f;
            float v01 = vlo ? acc[i][j][1] + b1 : 0.f;
            float v10 = vhi ? acc[i][j][2] + b0 : 0.f;
            float v11 = vhi ? acc[i][j][3] + b1 : 0.f;
            if (vlo) *(__half2*)&Y[(size_t)r_lo * 128 + c0] = __floats2half2_rn(v00, v01);
            if (vhi) *(__half2*)&Y[(size_t)r_hi * 128 + c0] = __floats2half2_rn(v10, v11);
            float s0 = v00 + v10, s1 = v01 + v11;
            float q0 = v00 * v00 + v10 * v10, q1 = v01 * v01 + v11 * v11;
#pragma unroll
            for (int off = 4; off <= 16; off <<= 1) {
                s0 += __shfl_xor_sync(0xFFFFFFFFu, s0, off);
                s1 += __shfl_xor_sync(0xFFFFFFFFu, s1, off);
                q0 += __shfl_xor_sync(0xFFFFFFFFu, q0, off);
                q1 += __shfl_xor_sync(0xFFFFFFFFu, q1, off);
            }
            if (rsel == 0) {
                atomicAdd(&sstat[c0], s0);
                atomicAdd(&sstat[c0 + 1], s1);
                atomicAdd(&sstat[128 + c0], q0);
                atomicAdd(&sstat[128 + c0 + 1], q1);
            }
        }
    }
    __syncthreads();
    atomicAdd(&stats[tid], sstat[tid]);
}

// ---------------- small MLP GEMM (thread-per-output) ----------------
__global__ void gemm_small_kernel(const float* __restrict__ X, const float* __restrict__ W,
                                  const float* __restrict__ bias, int R, int K, int C,
                                  float* __restrict__ Y, float* __restrict__ stats) {
    int c = blockIdx.x * 32 + (threadIdx.x & 31);
    int r = blockIdx.y * 8 + (threadIdx.x >> 5);
    if (c >= C || r >= R) return;
    float acc = bias[c];
    const float* xr = X + (size_t)r * K;
    for (int k = 0; k < K; ++k) acc = fmaf(xr[k], W[(size_t)k * C + c], acc);
    Y[(size_t)r * C + c] = acc;
    atomicAdd(&stats[c], acc);
    atomicAdd(&stats[C + c], acc * acc);
}

// norm+relu with BN finalize folded in
__global__ void norm_relu_kernel(float* __restrict__ Y, const float* __restrict__ stats,
                                 const float* __restrict__ gamma, const float* __restrict__ beta,
                                 float invn, int total, int C) {
    int i = blockIdx.x * blockDim.x + threadIdx.x;
    if (i >= total) return;
    int c = i % C;
    float mu = stats[c] * invn;
    float var = stats[C + c] * invn - mu * mu;
    float s = gamma[c] * rsqrtf(var + 1e-5f);
    float v = (Y[i] - mu) * s + beta[c];
    Y[i] = fmaxf(v, 0.f);
}

__global__ void fc2_kernel(const float* __restrict__ X, const float* __restrict__ W,
                           const float* __restrict__ bias, float* __restrict__ out) {
    int c = blockIdx.x * 32 + (threadIdx.x & 31);
    int g = blockIdx.y * 8 + (threadIdx.x >> 5);
    if (c >= NCOUT || g >= GG) return;
    float acc = bias[204 + c];
    const float* xr = X + (size_t)g * 256;
    for (int k = 0; k < 256; ++k) acc = fmaf(xr[k], W[(size_t)k * 408 + 204 + c], acc);
    out[(size_t)g * NCOUT + c] = 1.f / (1.f + expf(-acc));
}

// ---------------- host orchestration ----------------
extern "C" void kernel_launch(void* const* d_in, const int* in_sizes, int n_in,
                              void* d_out, int out_size) {
    const float* h        = (const float*)d_in[0];
    const int*   esrc     = (const int*)d_in[1];
    const int*   edst     = (const int*)d_in[2];
    const int*   gid      = (const int*)d_in[3];
    const float* W1       = (const float*)d_in[4];
    const float* b1       = (const float*)d_in[5];
    const float* g1_gamma = (const float*)d_in[6];
    const float* g1_beta  = (const float*)d_in[7];
    const float* Wg       = (const float*)d_in[8];
    const float* bg       = (const float*)d_in[9];
    const float* gg       = (const float*)d_in[10];
    const float* gb       = (const float*)d_in[11];
    const float* fc1_W    = (const float*)d_in[12];
    const float* fc1_b    = (const float*)d_in[13];
    const float* bn1_g    = (const float*)d_in[14];
    const float* bn1_b    = (const float*)d_in[15];
    const float* lin_W    = (const float*)d_in[16];
    const float* lin_b    = (const float*)d_in[17];
    const float* lbn_g    = (const float*)d_in[18];
    const float* lbn_b    = (const float*)d_in[19];
    const float* fc2_W    = (const float*)d_in[20];
    const float* fc2_b    = (const float*)d_in[21];
    float* out = (float*)d_out;

    float *stats, *xg, *m1, *m2;
    __half *bufT, *bufY, *bufX, *wt;
    int *rowptr;
    cudaGetSymbolAddress((void**)&bufT, g_bufT);
    cudaGetSymbolAddress((void**)&bufY, g_bufY);
    cudaGetSymbolAddress((void**)&bufX, g_bufX);
    cudaGetSymbolAddress((void**)&stats, g_stats);
    cudaGetSymbolAddress((void**)&xg, g_xg);
    cudaGetSymbolAddress((void**)&m1, g_m1);
    cudaGetSymbolAddress((void**)&m2, g_m2);
    cudaGetSymbolAddress((void**)&rowptr, g_rowptr);
    cudaGetSymbolAddress((void**)&wt, g_wt);

    const int SMEMMA = 2 * 128 * PITCH * 2 + 128 * 4 + 256 * 4;   // 71168
    cudaFuncSetAttribute(gemm_mma_kernel, cudaFuncAttributeMaxDynamicSharedMemorySize, SMEMMA);

    const int WB = (NN * 32 + 255) / 256;   // warp-per-node grids
    const int EB = (EE + 255) / 256;
    const int GBt = (NN + 127) / 128;       // 782 GEMM tiles
    const int BNB = 6250;

    // ---- CSR build + layer 0 (no memsets: zeroing folded into wcvt/hist) ----
    wcvt_kernel<<<64, 256>>>(W1, 78, wt, 1);     // also zeroes rowptr + stats
    hist_kernel<<<EB, 256>>>(edst);              // also zeroes cursor
    scan_kernel<<<1, 1024>>>(rowptr, NN + 1);
    fill_kernel<<<EB, 256>>>(esrc, edst);
    agg0_kernel<<<WB, 256>>>(h);
    gemm_mma_kernel<<<GBt, 256, SMEMMA>>>(bufT, wt, b1, 2.f, NN, bufY, stats);

    // ---- layers 1..4 ----
    const float* gmas[5] = {g1_gamma, gg, gg + 128, gg + 256, gg + 384};
    const float* btas[5] = {g1_beta,  gb, gb + 128, gb + 256, gb + 384};
    for (int l = 0; l < 4; ++l) {
        float* stPrev = stats + l * 1024;
        float* st = stats + (l + 1) * 1024;
        bnrelu_kernel<<<BNB, 256>>>(bufY, bufX, stPrev, gmas[l], btas[l]);
        agg_kernel<<<WB, 256>>>(bufX, bufT);
        wcvt_kernel<<<64, 256>>>(Wg + (size_t)l * 128 * 128, 128, wt, 0);
        gemm_mma_kernel<<<GBt, 256, SMEMMA>>>(bufT, wt, bg + l * 128, 2.f, NN, bufY, st);
    }

    // ---- fused BN + sorted segment-sum readout (no atomics, no X round-trip) ----
    readout_kernel<<<GG, 128>>>(bufY, gid, xg, stats + 4 * 1024, gmas[4], btas[4]);

    // ---- MLP head ----
    float* st5 = stats + 5 * 1024;
    float* st6 = stats + 6 * 1024;
    gemm_small_kernel<<<dim3(512 / 32, GG / 8), 256>>>(xg, fc1_W, fc1_b, GG, 128, 512, m1, st5);
    norm_relu_kernel<<<(GG * 512 + 255) / 256, 256>>>(m1, st5, bn1_g, bn1_b, 1.f / GG,
                                                      GG * 512, 512);

    gemm_small_kernel<<<dim3(256 / 32, GG / 8), 256>>>(m1, lin_W, lin_b, GG, 512, 256, m2, st6);
    norm_relu_kernel<<<(GG * 256 + 255) / 256, 256>>>(m2, st6, lbn_g, lbn_b, 1.f / GG,
                                                      GG * 256, 256);

    fc2_kernel<<<dim3(7, GG / 8), 256>>>(m2, fc2_W, fc2_b, out);
}